// round 12
// baseline (speedup 1.0000x reference)
#include <cuda_runtime.h>
#include <stdint.h>

#define B_  2
#define M_  2048
#define N_  2048
#define D_  1024
#define NH_ 16
#define DH_ 64

#define NIN ((size_t)B_ * M_ * D_)   // 4M elems
#define NW  ((size_t)D_ * D_)        // 1M elems

// Scratch (device globals: no allocation allowed).
// g_K / g_V are stored in MMA *fragment order* (see kfrag_idx / vfrag_idx).
__device__ float g_Q[NIN];           // tf32(Q*scale*log2e) bits, row-major
__device__ float g_K[NIN];           // tf32 bits, fragment order
__device__ float g_V[NIN];           // tf32 bits, fragment order
__device__ float g_C[NIN];           // tf32 bits (attention output), row-major
__device__ float g_Xq[NIN];          // tf32(query) bits
__device__ float g_Xkv[NIN];         // tf32(key_value) bits
__device__ float g_Wq[NW], g_Wk[NW], g_Wv[NW], g_Wo[NW];   // tf32(weight) bits
__device__ unsigned char g_mask[B_ * N_];

// ---------------------------------------------------------------------------
// helpers
// ---------------------------------------------------------------------------
__device__ __forceinline__ unsigned f2tf(float x) {
    unsigned u; asm("cvt.rna.tf32.f32 %0, %1;" : "=r"(u) : "f"(x)); return u;
}
__device__ __forceinline__ float ex2(float x) {
    float y; asm("ex2.approx.f32 %0, %1;" : "=f"(y) : "f"(x)); return y;
}
__device__ __forceinline__ void mma8(float* c, unsigned a0, unsigned a1, unsigned a2, unsigned a3,
                                     unsigned b0, unsigned b1) {
    asm volatile(
        "mma.sync.aligned.m16n8k8.row.col.f32.tf32.tf32.f32 "
        "{%0,%1,%2,%3},{%4,%5,%6,%7},{%8,%9},{%0,%1,%2,%3};\n"
        : "+f"(c[0]), "+f"(c[1]), "+f"(c[2]), "+f"(c[3])
        : "r"(a0), "r"(a1), "r"(a2), "r"(a3), "r"(b0), "r"(b1));
}
__device__ __forceinline__ void cpasync16(void* dst, const void* src) {
    unsigned d = (unsigned)__cvta_generic_to_shared(dst);
    asm volatile("cp.async.cg.shared.global [%0], [%1], 16;\n" :: "r"(d), "l"(src));
}
#define CP_COMMIT() asm volatile("cp.async.commit_group;\n" ::: "memory")
#define CP_WAIT0()  asm volatile("cp.async.wait_group 0;\n" ::: "memory")
#define CP_WAIT1()  asm volatile("cp.async.wait_group 1;\n" ::: "memory")
#define CP_WAIT2()  asm volatile("cp.async.wait_group 2;\n" ::: "memory")

#define SCQ (0.125f * 1.44269504f)   // 1/sqrt(dh) * log2(e), folded into Q

// Fragment-order index for K: (global row R in [0,4096), col c in [0,1024))
// -> word index into g_K. Per (b,h,ktile) 64x64 tile of 4096 words, laid out
// so thread lane's 4 b-operand words for (kk, ntp) are contiguous:
//   W = ((kk*4+ntp)*32 + lane)*4 + j,  lane = (key&7)*4 + (d&3),
//   j = ((key>>3)&1)*2 + ((d>>2)&1),   kk = d>>3, ntp = (key>>4)&3
__device__ __forceinline__ size_t kfrag_idx(int R, int c) {
    int b = R >> 11, key = R & 2047, kt = key >> 6, ky = key & 63;
    int h = c >> 6, d = c & 63;
    int W = (((d >> 3) * 4 + (ky >> 4)) * 32 + ((ky & 7) * 4 + (d & 3))) * 4
            + ((ky >> 3) & 1) * 2 + ((d >> 2) & 1);
    return ((size_t)((b * NH_ + h) * 32 + kt)) * 4096 + W;
}
// Fragment-order index for V (kk runs over keys, n over head-dim):
//   W = ((kk*4+ntp)*32 + lane)*4 + j, lane = (d&7)*4 + (key&3),
//   j = ((d>>3)&1)*2 + ((key>>2)&1),  kk = key>>3, ntp = (d>>4)&3
__device__ __forceinline__ size_t vfrag_idx(int R, int c) {
    int b = R >> 11, key = R & 2047, kt = key >> 6, ky = key & 63;
    int h = c >> 6, d = c & 63;
    int W = (((ky >> 3) * 4 + (d >> 4)) * 32 + ((d & 7) * 4 + (ky & 3))) * 4
            + ((d >> 3) & 1) * 2 + ((ky >> 2) & 1);
    return ((size_t)((b * NH_ + h) * 32 + kt)) * 4096 + W;
}

// ---------------------------------------------------------------------------
// Mask dtype sniffer + expander (bool may arrive as u8 / i32 / f32)
// ---------------------------------------------------------------------------
__global__ void mask_expand_kernel(const unsigned char* __restrict__ raw) {
    __shared__ int s_not_int, s_not_float;
    if (threadIdx.x == 0) { s_not_int = 0; s_not_float = 0; }
    __syncthreads();
    const unsigned int* w = (const unsigned int*)raw;
    for (int i = threadIdx.x; i < 1024; i += blockDim.x) {
        unsigned int x = w[i];
        if (x != 0u && x != 1u)          atomicOr(&s_not_int, 1);
        if (x != 0u && x != 0x3F800000u) atomicOr(&s_not_float, 1);
    }
    __syncthreads();
    int mode = (!s_not_int) ? 0 : ((!s_not_float) ? 1 : 2);
    if (mode == 2) {
        for (int i = threadIdx.x; i < B_ * N_; i += blockDim.x)
            g_mask[i] = raw[i] ? 1 : 0;
    } else {
        for (int i = threadIdx.x; i < B_ * N_; i += blockDim.x)
            g_mask[i] = w[i] ? 1 : 0;
    }
}

// ---------------------------------------------------------------------------
// One-time tf32 pre-rounding of all GEMM operands (inputs + weights).
// ---------------------------------------------------------------------------
__global__ __launch_bounds__(256) void preround_kernel(
    const float* __restrict__ q, const float* __restrict__ kv,
    const float* __restrict__ wq, const float* __restrict__ wk,
    const float* __restrict__ wv, const float* __restrict__ wo)
{
    size_t i4 = (size_t)blockIdx.x * blockDim.x + threadIdx.x;
    const size_t total4 = (2 * NIN + 4 * NW) / 4;   // 3,145,728
    if (i4 >= total4) return;
    size_t off = i4 * 4;
    const float* src; float* dst;
    if (off < NIN)                       { src = q;  dst = g_Xq;  }
    else if ((off -= NIN) < NIN)         { src = kv; dst = g_Xkv; }
    else if ((off -= NIN) < NW)          { src = wq; dst = g_Wq;  }
    else if ((off -= NW) < NW)           { src = wk; dst = g_Wk;  }
    else if ((off -= NW) < NW)           { src = wv; dst = g_Wv;  }
    else         { off -= NW;              src = wo; dst = g_Wo;  }
    float4 v = *(const float4*)(src + off);
    float4 r;
    r.x = __uint_as_float(f2tf(v.x));
    r.y = __uint_as_float(f2tf(v.y));
    r.z = __uint_as_float(f2tf(v.z));
    r.w = __uint_as_float(f2tf(v.w));
    *(float4*)(dst + off) = r;
}

// ---------------------------------------------------------------------------
// TF32 GEMM (2-stage cp.async), operands PRE-ROUNDED tf32 bits.
// 128x128 tile, BK=16, 256 thr, __launch_bounds__(256,2).
// Epilogue MODE: 0 = plain fp32, 2 = tf32(acc*SCQ) row-major,
//                3 = tf32 bits scattered to K fragment order,
//                4 = tf32 bits scattered to V fragment order.
// ---------------------------------------------------------------------------
#define GA_STR 20
#define GB_STR 136
#define GA_WORDS (128 * GA_STR)
#define GB_WORDS (16 * GB_STR)

__device__ __forceinline__ void gemm_stage_load(
    const float* __restrict__ A, const float* __restrict__ Bm,
    int rowBase, int colBase, int k0, float* As, float* Bs, int tid)
{
#pragma unroll
    for (int i = 0; i < 2; ++i) {
        int f = tid + i * 256;
        int r = f >> 2, c = (f & 3) * 4;
        cpasync16(As + r * GA_STR + c, A + (size_t)(rowBase + r) * D_ + k0 + c);
    }
#pragma unroll
    for (int i = 0; i < 2; ++i) {
        int f = tid + i * 256;
        int r = f >> 5, c = (f & 31) * 4;
        cpasync16(Bs + r * GB_STR + c, Bm + (size_t)(k0 + r) * D_ + colBase + c);
    }
}

template<int MODE>
__device__ __forceinline__ void gemm_body(
    const float* __restrict__ A, const float* __restrict__ Bm, float* __restrict__ C)
{
    __shared__ float As[2][GA_WORDS];
    __shared__ float Bs[2][GB_WORDS];

    const int tid  = threadIdx.x;
    const int warp = tid >> 5, lane = tid & 31;
    const int g = lane >> 2, t = lane & 3;
    const int wm = (warp >> 2) * 64;
    const int wn = (warp & 3) * 32;
    const int rowBase = blockIdx.y * 128;
    const int colBase = blockIdx.x * 128;

    float acc[4][4][4];
#pragma unroll
    for (int i = 0; i < 4; ++i)
#pragma unroll
        for (int j = 0; j < 4; ++j)
#pragma unroll
            for (int k = 0; k < 4; ++k) acc[i][j][k] = 0.f;

    gemm_stage_load(A, Bm, rowBase, colBase, 0, As[0], Bs[0], tid);
    CP_COMMIT();

    const int NIT = D_ / 16;   // 64
    for (int it = 0; it < NIT; ++it) {
        const int cur = it & 1;
        if (it + 1 < NIT) {
            gemm_stage_load(A, Bm, rowBase, colBase, (it + 1) * 16,
                            As[cur ^ 1], Bs[cur ^ 1], tid);
            CP_COMMIT();
            CP_WAIT1();
        } else {
            CP_WAIT0();
        }
        __syncthreads();

        const unsigned* Ac = (const unsigned*)As[cur];
        const unsigned* Bc = (const unsigned*)Bs[cur];
#pragma unroll
        for (int kk = 0; kk < 2; ++kk) {
            const int kb = kk * 8;
            unsigned a[4][4], bf[4][2];
#pragma unroll
            for (int mt = 0; mt < 4; ++mt) {
                int mr = wm + mt * 16;
                a[mt][0] = Ac[(mr + g) * GA_STR + kb + t];
                a[mt][1] = Ac[(mr + g + 8) * GA_STR + kb + t];
                a[mt][2] = Ac[(mr + g) * GA_STR + kb + t + 4];
                a[mt][3] = Ac[(mr + g + 8) * GA_STR + kb + t + 4];
            }
#pragma unroll
            for (int nt = 0; nt < 4; ++nt) {
                int nc = wn + nt * 8 + g;
                bf[nt][0] = Bc[(kb + t) * GB_STR + nc];
                bf[nt][1] = Bc[(kb + t + 4) * GB_STR + nc];
            }
#pragma unroll
            for (int mt = 0; mt < 4; ++mt)
#pragma unroll
                for (int nt = 0; nt < 4; ++nt)
                    mma8(acc[mt][nt], a[mt][0], a[mt][1], a[mt][2], a[mt][3],
                         bf[nt][0], bf[nt][1]);
        }
        __syncthreads();
    }

#pragma unroll
    for (int mt = 0; mt < 4; ++mt) {
        int r0 = rowBase + wm + mt * 16 + g;
#pragma unroll
        for (int nt = 0; nt < 4; ++nt) {
            int c0 = colBase + wn + nt * 8 + 2 * t;
            float v0 = acc[mt][nt][0], v1 = acc[mt][nt][1];
            float v2 = acc[mt][nt][2], v3 = acc[mt][nt][3];
            if (MODE == 0) {
                *(float2*)(C + (size_t)r0 * D_ + c0)       = make_float2(v0, v1);
                *(float2*)(C + (size_t)(r0 + 8) * D_ + c0) = make_float2(v2, v3);
            } else if (MODE == 2) {
                v0 = __uint_as_float(f2tf(v0 * SCQ));
                v1 = __uint_as_float(f2tf(v1 * SCQ));
                v2 = __uint_as_float(f2tf(v2 * SCQ));
                v3 = __uint_as_float(f2tf(v3 * SCQ));
                *(float2*)(C + (size_t)r0 * D_ + c0)       = make_float2(v0, v1);
                *(float2*)(C + (size_t)(r0 + 8) * D_ + c0) = make_float2(v2, v3);
            } else if (MODE == 3) {
                C[kfrag_idx(r0,     c0)]     = __uint_as_float(f2tf(v0));
                C[kfrag_idx(r0,     c0 + 1)] = __uint_as_float(f2tf(v1));
                C[kfrag_idx(r0 + 8, c0)]     = __uint_as_float(f2tf(v2));
                C[kfrag_idx(r0 + 8, c0 + 1)] = __uint_as_float(f2tf(v3));
            } else {  // MODE 4
                C[vfrag_idx(r0,     c0)]     = __uint_as_float(f2tf(v0));
                C[vfrag_idx(r0,     c0 + 1)] = __uint_as_float(f2tf(v1));
                C[vfrag_idx(r0 + 8, c0)]     = __uint_as_float(f2tf(v2));
                C[vfrag_idx(r0 + 8, c0 + 1)] = __uint_as_float(f2tf(v3));
            }
        }
    }
}

__global__ __launch_bounds__(256, 2) void gemm_qkv()
{
    if (blockIdx.z == 0)      gemm_body<2>(g_Xq,  g_Wq, g_Q);
    else if (blockIdx.z == 1) gemm_body<3>(g_Xkv, g_Wk, g_K);
    else                      gemm_body<4>(g_Xkv, g_Wv, g_V);
}

__global__ __launch_bounds__(256, 2) void gemm_out(float* __restrict__ out)
{
    gemm_body<0>(g_C, g_Wo, out);
}

// ---------------------------------------------------------------------------
// TF32 flash attention: fragment-order K/V in smem -> b-operands via LDS.128
// (one uint4 feeds 4 MMAs). Two m16 tiles per warp (32 rows), Q in registers,
// P relayout via shuffles, K double-buffered + V single-buffered cp.async.
// Block = 128 rows, 4 warps. Grid: (M/128, NH, B). __launch_bounds__(128,2).
// ---------------------------------------------------------------------------
#define KV_WORDS 4096
#define AK_OFF 0
#define AV_OFF (2 * KV_WORDS)                   // 8192
#define AMB_OFF (AV_OFF + KV_WORDS)             // 12288
#define ATT_WORDS (AMB_OFF + 64)                // 12352 words = 49408 B

#define M_INIT (-1.0e4f)
#define MASK_BIAS (-1.0e9f)

__global__ __launch_bounds__(128, 2) void attn_tc(
    const float* __restrict__ Q, const float* __restrict__ K,
    const float* __restrict__ V, float* __restrict__ Cout)
{
    extern __shared__ unsigned smemu[];
    unsigned* Kr = smemu + AK_OFF;        // fragment-order tf32 bits, 2 stages
    unsigned* Vr = smemu + AV_OFF;        // fragment-order tf32 bits, 1 stage
    float* mbias = (float*)(smemu + AMB_OFF);

    const int mtile = blockIdx.x, h = blockIdx.y, b = blockIdx.z;
    const int tid = threadIdx.x;
    const int warp = tid >> 5, lane = tid & 31;
    const int g = lane >> 2, t = lane & 3;
    const int mb = warp * 32;             // 32 query rows per warp
    const unsigned srcA = (unsigned)((lane & 28) | (t >> 1));   // quad-local source
    const bool oddt = (t & 1);

    const unsigned* Kbase = (const unsigned*)K + ((size_t)(b * NH_ + h) * 32) * KV_WORDS;
    const unsigned* Vbase = (const unsigned*)V + ((size_t)(b * NH_ + h) * 32) * KV_WORDS;
    const int ld = tid * 32;              // this thread's flat copy offset

    // Preload: group{K0}, group{V0} (flat copies; layout is pre-permuted)
    {
#pragma unroll
        for (int i = 0; i < 8; ++i) cpasync16(Kr + ld + i * 4, Kbase + ld + i * 4);
        CP_COMMIT();
#pragma unroll
        for (int i = 0; i < 8; ++i) cpasync16(Vr + ld + i * 4, Vbase + ld + i * 4);
        CP_COMMIT();
    }

    // Q a-fragments for BOTH m-tiles (row-major g_Q, pre-rounded+scaled bits)
    unsigned qa[2][8][4];
#pragma unroll
    for (int u = 0; u < 2; ++u) {
        const unsigned* q0 = (const unsigned*)(Q + ((size_t)(b * M_ + mtile * 128 + mb + u * 16 + g)) * D_ + h * DH_);
        const unsigned* q1 = (const unsigned*)(Q + ((size_t)(b * M_ + mtile * 128 + mb + u * 16 + g + 8)) * D_ + h * DH_);
#pragma unroll
        for (int kk = 0; kk < 8; ++kk) {
            const int kb = kk * 8;
            qa[u][kk][0] = q0[kb + t];
            qa[u][kk][1] = q1[kb + t];
            qa[u][kk][2] = q0[kb + t + 4];
            qa[u][kk][3] = q1[kb + t + 4];
        }
    }

    float mS[2][2], lS[2][2];
#pragma unroll
    for (int u = 0; u < 2; ++u) { mS[u][0] = M_INIT; mS[u][1] = M_INIT; lS[u][0] = 0.f; lS[u][1] = 0.f; }
    float o[2][8][4];
#pragma unroll
    for (int u = 0; u < 2; ++u)
#pragma unroll
        for (int i = 0; i < 8; ++i)
#pragma unroll
            for (int j = 0; j < 4; ++j) o[u][i][j] = 0.f;

    const int NT = N_ / 64;  // 32
    for (int kt = 0; kt < NT; ++kt) {
        const int cur = kt & 1;
        if (tid < 64)
            mbias[tid] = g_mask[b * N_ + kt * 64 + tid] ? MASK_BIAS : 0.f;
        // prefetch K(kt+1)
        if (kt + 1 < NT) {
            const unsigned* ks = Kbase + (size_t)(kt + 1) * KV_WORDS + ld;
            unsigned* kd = Kr + (cur ^ 1) * KV_WORDS + ld;
#pragma unroll
            for (int i = 0; i < 8; ++i) cpasync16(kd + i * 4, ks + i * 4);
            CP_COMMIT();
            CP_WAIT2();     // K(kt) complete; V(kt), K(kt+1) may fly
        } else {
            CP_WAIT1();     // only V(NT-1) may remain outstanding
        }
        __syncthreads();    // K(kt) + mbias visible

        const unsigned* Kc = Kr + cur * KV_WORDS;

        // S = Q K^T — one LDS.128 feeds 4 MMAs (2 nt x 2 m-tiles)
        float s[2][8][4];
#pragma unroll
        for (int u = 0; u < 2; ++u)
#pragma unroll
            for (int i = 0; i < 8; ++i)
#pragma unroll
                for (int j = 0; j < 4; ++j) s[u][i][j] = 0.f;

#pragma unroll
        for (int kk = 0; kk < 8; ++kk) {
#pragma unroll
            for (int ntp = 0; ntp < 4; ++ntp) {
                uint4 bv = *(const uint4*)(Kc + ((kk * 4 + ntp) * 32 + lane) * 4);
                const int nt0 = 2 * ntp, nt1 = nt0 + 1;
                mma8(s[0][nt0], qa[0][kk][0], qa[0][kk][1], qa[0][kk][2], qa[0][kk][3], bv.x, bv.y);
                mma8(s[1][nt0], qa[1][kk][0], qa[1][kk][1], qa[1][kk][2], qa[1][kk][3], bv.x, bv.y);
                mma8(s[0][nt1], qa[0][kk][0], qa[0][kk][1], qa[0][kk][2], qa[0][kk][3], bv.z, bv.w);
                mma8(s[1][nt1], qa[1][kk][0], qa[1][kk][1], qa[1][kk][2], qa[1][kk][3], bv.z, bv.w);
            }
        }

        // online softmax (base-2), independent per m-tile
#pragma unroll
        for (int u = 0; u < 2; ++u) {
            float mx0 = -3.0e38f, mx1 = -3.0e38f;
#pragma unroll
            for (int nt = 0; nt < 8; ++nt) {
                float b0 = mbias[nt * 8 + 2 * t];
                float b1 = mbias[nt * 8 + 2 * t + 1];
                s[u][nt][0] += b0; s[u][nt][1] += b1;
                s[u][nt][2] += b0; s[u][nt][3] += b1;
                mx0 = fmaxf(mx0, fmaxf(s[u][nt][0], s[u][nt][1]));
                mx1 = fmaxf(mx1, fmaxf(s[u][nt][2], s[u][nt][3]));
            }
            mx0 = fmaxf(mx0, __shfl_xor_sync(0xFFFFFFFFu, mx0, 1));
            mx0 = fmaxf(mx0, __shfl_xor_sync(0xFFFFFFFFu, mx0, 2));
            mx1 = fmaxf(mx1, __shfl_xor_sync(0xFFFFFFFFu, mx1, 1));
            mx1 = fmaxf(mx1, __shfl_xor_sync(0xFFFFFFFFu, mx1, 2));
            float nm0 = fmaxf(mS[u][0], mx0), nm1 = fmaxf(mS[u][1], mx1);
            float cr0 = ex2(mS[u][0] - nm0), cr1 = ex2(mS[u][1] - nm1);
            mS[u][0] = nm0; mS[u][1] = nm1;

            float rs0 = 0.f, rs1 = 0.f;
#pragma unroll
            for (int nt = 0; nt < 8; ++nt) {
                s[u][nt][0] = ex2(s[u][nt][0] - nm0);
                s[u][nt][1] = ex2(s[u][nt][1] - nm0);
                s[u][nt][2] = ex2(s[u][nt][2] - nm1);
                s[u][nt][3] = ex2(s[u][nt][3] - nm1);
                rs0 += s[u][nt][0] + s[u][nt][1];
                rs1 += s[u][nt][2] + s[u][nt][3];
                o[u][nt][0] *= cr0; o[u][nt][1] *= cr0;
                o[u][nt][2] *= cr1; o[u][nt][3] *= cr1;
            }
            lS[u][0] = lS[u][0] * cr0 + rs0;
            lS[u][1] = lS[u][1] * cr1 + rs1;
        }

        // V(kt) must be complete before PV
        if (kt + 1 < NT) CP_WAIT1(); else CP_WAIT0();
        __syncthreads();    // V(kt) visible

        // O += P V — P via intra-quad shuffles; one LDS.128 feeds 4 MMAs
#pragma unroll
        for (int kk = 0; kk < 8; ++kk) {
            unsigned a[2][4];
#pragma unroll
            for (int u = 0; u < 2; ++u) {
                float v00 = __shfl_sync(0xFFFFFFFFu, s[u][kk][0], srcA);
                float v01 = __shfl_sync(0xFFFFFFFFu, s[u][kk][1], srcA);
                float v20 = __shfl_sync(0xFFFFFFFFu, s[u][kk][2], srcA);
                float v21 = __shfl_sync(0xFFFFFFFFu, s[u][kk][3], srcA);
                float w00 = __shfl_sync(0xFFFFFFFFu, s[u][kk][0], srcA + 2);
                float w01 = __shfl_sync(0xFFFFFFFFu, s[u][kk][1], srcA + 2);
                float w20 = __shfl_sync(0xFFFFFFFFu, s[u][kk][2], srcA + 2);
                float w21 = __shfl_sync(0xFFFFFFFFu, s[u][kk][3], srcA + 2);
                a[u][0] = f2tf(oddt ? v01 : v00);
                a[u][1] = f2tf(oddt ? v21 : v20);
                a[u][2] = f2tf(oddt ? w01 : w00);
                a[u][3] = f2tf(oddt ? w21 : w20);
            }
#pragma unroll
            for (int ntp = 0; ntp < 4; ++ntp) {
                uint4 bv = *(const uint4*)(Vr + ((kk * 4 + ntp) * 32 + lane) * 4);
                const int nt0 = 2 * ntp, nt1 = nt0 + 1;
                mma8(o[0][nt0], a[0][0], a[0][1], a[0][2], a[0][3], bv.x, bv.y);
                mma8(o[1][nt0], a[1][0], a[1][1], a[1][2], a[1][3], bv.x, bv.y);
                mma8(o[0][nt1], a[0][0], a[0][1], a[0][2], a[0][3], bv.z, bv.w);
                mma8(o[1][nt1], a[1][0], a[1][1], a[1][2], a[1][3], bv.z, bv.w);
            }
        }
        __syncthreads();    // all PV reads done -> V buffer free, K stage free

        // prefetch V(kt+1) into the (single) V buffer
        if (kt + 1 < NT) {
            const unsigned* vs = Vbase + (size_t)(kt + 1) * KV_WORDS + ld;
#pragma unroll
            for (int i = 0; i < 8; ++i) cpasync16(Vr + ld + i * 4, vs + i * 4);
            CP_COMMIT();
        }
    }

    // finalize both m-tiles
#pragma unroll
    for (int u = 0; u < 2; ++u) {
        float l0 = lS[u][0], l1 = lS[u][1];
        l0 += __shfl_xor_sync(0xFFFFFFFFu, l0, 1);
        l0 += __shfl_xor_sync(0xFFFFFFFFu, l0, 2);
        l1 += __shfl_xor_sync(0xFFFFFFFFu, l1, 1);
        l1 += __shfl_xor_sync(0xFFFFFFFFu, l1, 2);
        float inv0 = 1.f / l0, inv1 = 1.f / l1;

        const int gr0 = mtile * 128 + mb + u * 16 + g;
        const int gr1 = gr0 + 8;
#pragma unroll
        for (int nt = 0; nt < 8; ++nt) {
            int col = h * DH_ + nt * 8 + 2 * t;
            *(float2*)(Cout + ((size_t)(b * M_ + gr0)) * D_ + col) =
                make_float2(__uint_as_float(f2tf(o[u][nt][0] * inv0)),
                            __uint_as_float(f2tf(o[u][nt][1] * inv0)));
            *(float2*)(Cout + ((size_t)(b * M_ + gr1)) * D_ + col) =
                make_float2(__uint_as_float(f2tf(o[u][nt][2] * inv1)),
                            __uint_as_float(f2tf(o[u][nt][3] * inv1)));
        }
    }
}

// ---------------------------------------------------------------------------
// Launch. Inputs: query, key_value, key_padding_mask, W_Q, W_K, W_V, W_O
// ---------------------------------------------------------------------------
extern "C" void kernel_launch(void* const* d_in, const int* in_sizes, int n_in,
                              void* d_out, int out_size)
{
    const float* query = (const float*)d_in[0];
    const float* keyv  = (const float*)d_in[1];
    const unsigned char* mask_raw = (const unsigned char*)d_in[2];
    const float* W_Q = (const float*)d_in[3];
    const float* W_K = (const float*)d_in[4];
    const float* W_V = (const float*)d_in[5];
    const float* W_O = (const float*)d_in[6];
    float* out = (float*)d_out;

    float *gQ, *gK, *gV, *gC;
    cudaGetSymbolAddress((void**)&gQ, g_Q);
    cudaGetSymbolAddress((void**)&gK, g_K);
    cudaGetSymbolAddress((void**)&gV, g_V);
    cudaGetSymbolAddress((void**)&gC, g_C);

    cudaFuncSetAttribute(attn_tc, cudaFuncAttributeMaxDynamicSharedMemorySize,
                         ATT_WORDS * 4);

    mask_expand_kernel<<<1, 1024>>>(mask_raw);

    // one-time tf32 pre-rounding of GEMM operands
    {
        const size_t total4 = (2 * NIN + 4 * NW) / 4;
        int blocks = (int)((total4 + 255) / 256);
        preround_kernel<<<blocks, 256>>>(query, keyv, W_Q, W_K, W_V, W_O);
    }

    dim3 gqkv(D_ / 128, (B_ * M_) / 128, 3);
    gemm_qkv<<<gqkv, 256>>>();

    dim3 gattn(M_ / 128, NH_, B_);
    attn_tc<<<gattn, 128, ATT_WORDS * 4>>>(gQ, gK, gV, gC);

    dim3 gout(D_ / 128, (B_ * M_) / 128);
    gemm_out<<<gout, 256>>>(out);
}

// round 13
// speedup vs baseline: 1.4515x; 1.4515x over previous
#include <cuda_runtime.h>
#include <cuda_fp16.h>
#include <stdint.h>

#define B_  2
#define M_  2048
#define N_  2048
#define D_  1024
#define NH_ 16
#define DH_ 64

#define NIN ((size_t)B_ * M_ * D_)   // 4M elems
#define NW  ((size_t)D_ * D_)        // 1M elems

// Scratch (device globals: no allocation allowed).
// g_Q: fp16(Q*scale*log2e) row-major (half2 words). g_K/g_V: fp16 in MMA
// fragment order (see kfrag_word / vfrag_half). g_C: tf32-rounded fp32.
__device__ float g_Q[NIN];
__device__ float g_K[NIN];
__device__ float g_V[NIN];
__device__ float g_C[NIN];
__device__ float g_Xq[NIN];          // tf32(query) bits
__device__ float g_Xkv[NIN];         // tf32(key_value) bits
__device__ float g_Wq[NW], g_Wk[NW], g_Wv[NW], g_Wo[NW];   // tf32(weight) bits
__device__ unsigned char g_mask[B_ * N_];

// ---------------------------------------------------------------------------
// helpers
// ---------------------------------------------------------------------------
__device__ __forceinline__ unsigned f2tf(float x) {
    unsigned u; asm("cvt.rna.tf32.f32 %0, %1;" : "=r"(u) : "f"(x)); return u;
}
__device__ __forceinline__ float ex2(float x) {
    float y; asm("ex2.approx.f32 %0, %1;" : "=f"(y) : "f"(x)); return y;
}
// pack two f32 -> f16x2 (lo = first elem)
__device__ __forceinline__ unsigned h2pack(float lo, float hi) {
    unsigned d;
    asm("cvt.rn.f16x2.f32 %0, %1, %2;" : "=r"(d) : "f"(hi), "f"(lo));
    return d;
}
// tf32 m16n8k8 (projection GEMMs)
__device__ __forceinline__ void mma8(float* c, unsigned a0, unsigned a1, unsigned a2, unsigned a3,
                                     unsigned b0, unsigned b1) {
    asm volatile(
        "mma.sync.aligned.m16n8k8.row.col.f32.tf32.tf32.f32 "
        "{%0,%1,%2,%3},{%4,%5,%6,%7},{%8,%9},{%0,%1,%2,%3};\n"
        : "+f"(c[0]), "+f"(c[1]), "+f"(c[2]), "+f"(c[3])
        : "r"(a0), "r"(a1), "r"(a2), "r"(a3), "r"(b0), "r"(b1));
}
// fp16 m16n8k16 (attention)
__device__ __forceinline__ void mma16(float* c, const unsigned* a, unsigned b0, unsigned b1) {
    asm volatile(
        "mma.sync.aligned.m16n8k16.row.col.f32.f16.f16.f32 "
        "{%0,%1,%2,%3},{%4,%5,%6,%7},{%8,%9},{%0,%1,%2,%3};\n"
        : "+f"(c[0]), "+f"(c[1]), "+f"(c[2]), "+f"(c[3])
        : "r"(a[0]), "r"(a[1]), "r"(a[2]), "r"(a[3]), "r"(b0), "r"(b1));
}
__device__ __forceinline__ void cpasync16(void* dst, const void* src) {
    unsigned d = (unsigned)__cvta_generic_to_shared(dst);
    asm volatile("cp.async.cg.shared.global [%0], [%1], 16;\n" :: "r"(d), "l"(src));
}
#define CP_COMMIT() asm volatile("cp.async.commit_group;\n" ::: "memory")
#define CP_WAIT0()  asm volatile("cp.async.wait_group 0;\n" ::: "memory")
#define CP_WAIT1()  asm volatile("cp.async.wait_group 1;\n" ::: "memory")

#define SCQ (0.125f * 1.44269504f)   // 1/sqrt(dh) * log2(e), folded into Q

// ---------------------------------------------------------------------------
// fp16 fragment-order indices.
// K (QK B-operand, m16n8k16): element (key ky, dim d) of a 64x64 tile.
//   b0 covers d%16 in [0,8): word j=(nt&1)*2; b1 covers [8,16): j+1.
//   lane = (ky&7)*4 + ((d&7)>>1), halves along d (d even = lo).
// Returns u32-word index (covers d, d+1), c must be even.
__device__ __forceinline__ size_t kfrag_word(int R, int c) {
    int b = R >> 11, key = R & 2047, kt = key >> 6, ky = key & 63;
    int h = c >> 6, d = c & 63;
    int kk = d >> 4, dd = d & 15;
    int bsel = dd >> 3, tq = (dd & 7) >> 1;
    int nt = ky >> 3, g = ky & 7;
    int lane = g * 4 + tq;
    int ntp = nt >> 1, j = (nt & 1) * 2 + bsel;
    int word = ((kk * 4 + ntp) * 32 + lane) * 4 + j;
    return ((size_t)((b * NH_ + h) * 32 + kt)) * 2048 + word;
}
// V (PV B-operand): element (key ky, dim d); halves along ky (ky even = lo).
__device__ __forceinline__ size_t vfrag_half(int R, int c) {
    int b = R >> 11, key = R & 2047, kt = key >> 6, ky = key & 63;
    int h = c >> 6, d = c & 63;
    int kk = ky >> 4, kyd = ky & 15;
    int bsel = kyd >> 3, tq = (kyd & 7) >> 1, hs = kyd & 1;
    int nt = d >> 3, g = d & 7;
    int lane = g * 4 + tq;
    int ntp = nt >> 1, j = (nt & 1) * 2 + bsel;
    int word = ((kk * 4 + ntp) * 32 + lane) * 4 + j;
    return ((size_t)((b * NH_ + h) * 32 + kt)) * 4096 + (size_t)word * 2 + hs;
}

// ---------------------------------------------------------------------------
// Mask dtype sniffer + expander (bool may arrive as u8 / i32 / f32)
// ---------------------------------------------------------------------------
__global__ void mask_expand_kernel(const unsigned char* __restrict__ raw) {
    __shared__ int s_not_int, s_not_float;
    if (threadIdx.x == 0) { s_not_int = 0; s_not_float = 0; }
    __syncthreads();
    const unsigned int* w = (const unsigned int*)raw;
    for (int i = threadIdx.x; i < 1024; i += blockDim.x) {
        unsigned int x = w[i];
        if (x != 0u && x != 1u)          atomicOr(&s_not_int, 1);
        if (x != 0u && x != 0x3F800000u) atomicOr(&s_not_float, 1);
    }
    __syncthreads();
    int mode = (!s_not_int) ? 0 : ((!s_not_float) ? 1 : 2);
    if (mode == 2) {
        for (int i = threadIdx.x; i < B_ * N_; i += blockDim.x)
            g_mask[i] = raw[i] ? 1 : 0;
    } else {
        for (int i = threadIdx.x; i < B_ * N_; i += blockDim.x)
            g_mask[i] = w[i] ? 1 : 0;
    }
}

// ---------------------------------------------------------------------------
// One-time tf32 pre-rounding of all GEMM operands (inputs + weights).
// ---------------------------------------------------------------------------
__global__ __launch_bounds__(256) void preround_kernel(
    const float* __restrict__ q, const float* __restrict__ kv,
    const float* __restrict__ wq, const float* __restrict__ wk,
    const float* __restrict__ wv, const float* __restrict__ wo)
{
    size_t i4 = (size_t)blockIdx.x * blockDim.x + threadIdx.x;
    const size_t total4 = (2 * NIN + 4 * NW) / 4;
    if (i4 >= total4) return;
    size_t off = i4 * 4;
    const float* src; float* dst;
    if (off < NIN)                       { src = q;  dst = g_Xq;  }
    else if ((off -= NIN) < NIN)         { src = kv; dst = g_Xkv; }
    else if ((off -= NIN) < NW)          { src = wq; dst = g_Wq;  }
    else if ((off -= NW) < NW)           { src = wk; dst = g_Wk;  }
    else if ((off -= NW) < NW)           { src = wv; dst = g_Wv;  }
    else         { off -= NW;              src = wo; dst = g_Wo;  }
    float4 v = *(const float4*)(src + off);
    float4 r;
    r.x = __uint_as_float(f2tf(v.x));
    r.y = __uint_as_float(f2tf(v.y));
    r.z = __uint_as_float(f2tf(v.z));
    r.w = __uint_as_float(f2tf(v.w));
    *(float4*)(dst + off) = r;
}

// ---------------------------------------------------------------------------
// TF32 GEMM (2-stage cp.async), operands PRE-ROUNDED tf32 bits.
// Epilogue MODE: 0 = plain fp32, 2 = fp16(acc*SCQ) row-major half2,
//                3 = fp16 K fragment order, 4 = fp16 V fragment order.
// ---------------------------------------------------------------------------
#define GA_STR 20
#define GB_STR 136
#define GA_WORDS (128 * GA_STR)
#define GB_WORDS (16 * GB_STR)

__device__ __forceinline__ void gemm_stage_load(
    const float* __restrict__ A, const float* __restrict__ Bm,
    int rowBase, int colBase, int k0, float* As, float* Bs, int tid)
{
#pragma unroll
    for (int i = 0; i < 2; ++i) {
        int f = tid + i * 256;
        int r = f >> 2, c = (f & 3) * 4;
        cpasync16(As + r * GA_STR + c, A + (size_t)(rowBase + r) * D_ + k0 + c);
    }
#pragma unroll
    for (int i = 0; i < 2; ++i) {
        int f = tid + i * 256;
        int r = f >> 5, c = (f & 31) * 4;
        cpasync16(Bs + r * GB_STR + c, Bm + (size_t)(k0 + r) * D_ + colBase + c);
    }
}

template<int MODE>
__device__ __forceinline__ void gemm_body(
    const float* __restrict__ A, const float* __restrict__ Bm, float* __restrict__ C)
{
    __shared__ float As[2][GA_WORDS];
    __shared__ float Bs[2][GB_WORDS];

    const int tid  = threadIdx.x;
    const int warp = tid >> 5, lane = tid & 31;
    const int g = lane >> 2, t = lane & 3;
    const int wm = (warp >> 2) * 64;
    const int wn = (warp & 3) * 32;
    const int rowBase = blockIdx.y * 128;
    const int colBase = blockIdx.x * 128;

    float acc[4][4][4];
#pragma unroll
    for (int i = 0; i < 4; ++i)
#pragma unroll
        for (int j = 0; j < 4; ++j)
#pragma unroll
            for (int k = 0; k < 4; ++k) acc[i][j][k] = 0.f;

    gemm_stage_load(A, Bm, rowBase, colBase, 0, As[0], Bs[0], tid);
    CP_COMMIT();

    const int NIT = D_ / 16;   // 64
    for (int it = 0; it < NIT; ++it) {
        const int cur = it & 1;
        if (it + 1 < NIT) {
            gemm_stage_load(A, Bm, rowBase, colBase, (it + 1) * 16,
                            As[cur ^ 1], Bs[cur ^ 1], tid);
            CP_COMMIT();
            CP_WAIT1();
        } else {
            CP_WAIT0();
        }
        __syncthreads();

        const unsigned* Ac = (const unsigned*)As[cur];
        const unsigned* Bc = (const unsigned*)Bs[cur];
#pragma unroll
        for (int kk = 0; kk < 2; ++kk) {
            const int kb = kk * 8;
            unsigned a[4][4], bf[4][2];
#pragma unroll
            for (int mt = 0; mt < 4; ++mt) {
                int mr = wm + mt * 16;
                a[mt][0] = Ac[(mr + g) * GA_STR + kb + t];
                a[mt][1] = Ac[(mr + g + 8) * GA_STR + kb + t];
                a[mt][2] = Ac[(mr + g) * GA_STR + kb + t + 4];
                a[mt][3] = Ac[(mr + g + 8) * GA_STR + kb + t + 4];
            }
#pragma unroll
            for (int nt = 0; nt < 4; ++nt) {
                int nc = wn + nt * 8 + g;
                bf[nt][0] = Bc[(kb + t) * GB_STR + nc];
                bf[nt][1] = Bc[(kb + t + 4) * GB_STR + nc];
            }
#pragma unroll
            for (int mt = 0; mt < 4; ++mt)
#pragma unroll
                for (int nt = 0; nt < 4; ++nt)
                    mma8(acc[mt][nt], a[mt][0], a[mt][1], a[mt][2], a[mt][3],
                         bf[nt][0], bf[nt][1]);
        }
        __syncthreads();
    }

#pragma unroll
    for (int mt = 0; mt < 4; ++mt) {
        int r0 = rowBase + wm + mt * 16 + g;
#pragma unroll
        for (int nt = 0; nt < 4; ++nt) {
            int c0 = colBase + wn + nt * 8 + 2 * t;
            float v0 = acc[mt][nt][0], v1 = acc[mt][nt][1];
            float v2 = acc[mt][nt][2], v3 = acc[mt][nt][3];
            if (MODE == 0) {
                *(float2*)(C + (size_t)r0 * D_ + c0)       = make_float2(v0, v1);
                *(float2*)(C + (size_t)(r0 + 8) * D_ + c0) = make_float2(v2, v3);
            } else if (MODE == 2) {
                unsigned* Ch = (unsigned*)C;
                Ch[((size_t)r0 * D_ + c0) >> 1]       = h2pack(v0 * SCQ, v1 * SCQ);
                Ch[((size_t)(r0 + 8) * D_ + c0) >> 1] = h2pack(v2 * SCQ, v3 * SCQ);
            } else if (MODE == 3) {
                unsigned* Ch = (unsigned*)C;
                Ch[kfrag_word(r0, c0)]     = h2pack(v0, v1);
                Ch[kfrag_word(r0 + 8, c0)] = h2pack(v2, v3);
            } else {  // MODE 4
                __half* Chh = (__half*)C;
                Chh[vfrag_half(r0,     c0)]     = __float2half_rn(v0);
                Chh[vfrag_half(r0,     c0 + 1)] = __float2half_rn(v1);
                Chh[vfrag_half(r0 + 8, c0)]     = __float2half_rn(v2);
                Chh[vfrag_half(r0 + 8, c0 + 1)] = __float2half_rn(v3);
            }
        }
    }
}

__global__ __launch_bounds__(256, 2) void gemm_qkv()
{
    if (blockIdx.z == 0)      gemm_body<2>(g_Xq,  g_Wq, g_Q);
    else if (blockIdx.z == 1) gemm_body<3>(g_Xkv, g_Wk, g_K);
    else                      gemm_body<4>(g_Xkv, g_Wv, g_V);
}

__global__ __launch_bounds__(256, 2) void gemm_out(float* __restrict__ out)
{
    gemm_body<0>(g_C, g_Wo, out);
}

// ---------------------------------------------------------------------------
// FP16 flash attention (m16n8k16): 2 m-tiles/warp, Q fragments in registers,
// P packs straight from S c-fragments (no shuffles), K+V double-buffered
// cp.async (one commit group per tile, one sync per tile).
// Block = 128 rows, 4 warps. Grid: (M/128, NH, B). Smem 33KB, (128,2).
// ---------------------------------------------------------------------------
#define KV_WORDS 2048
#define AK_OFF 0
#define AV_OFF (2 * KV_WORDS)                   // 4096
#define AMB_OFF (AV_OFF + 2 * KV_WORDS)         // 8192
#define ATT_WORDS (AMB_OFF + 64)                // 8256 words = 33024 B

#define M_INIT (-1.0e4f)
#define MASK_BIAS (-1.0e9f)

__global__ __launch_bounds__(128, 2) void attn_tc(
    const float* __restrict__ Q, const float* __restrict__ K,
    const float* __restrict__ V, float* __restrict__ Cout)
{
    extern __shared__ unsigned smemu[];
    unsigned* Kr = smemu + AK_OFF;        // fp16 fragment order, 2 stages
    unsigned* Vr = smemu + AV_OFF;        // fp16 fragment order, 2 stages
    float* mbias = (float*)(smemu + AMB_OFF);

    const int mtile = blockIdx.x, h = blockIdx.y, b = blockIdx.z;
    const int tid = threadIdx.x;
    const int warp = tid >> 5, lane = tid & 31;
    const int g = lane >> 2, t = lane & 3;
    const int mb = warp * 32;             // 32 query rows per warp

    const size_t tilebase = ((size_t)(b * NH_ + h) * 32) * KV_WORDS;
    const unsigned* Kbase = (const unsigned*)K + tilebase;
    const unsigned* Vbase = (const unsigned*)V + tilebase;
    const int ld = tid * 16;              // flat copy offset (2048 words/tile)

    // Preload K0+V0 (one group)
    {
#pragma unroll
        for (int i = 0; i < 4; ++i) cpasync16(Kr + ld + i * 4, Kbase + ld + i * 4);
#pragma unroll
        for (int i = 0; i < 4; ++i) cpasync16(Vr + ld + i * 4, Vbase + ld + i * 4);
    }
    CP_COMMIT();

    // Q a-fragments (fp16, pre-scaled): 4 regs per (u, kk), kk over d-chunks of 16
    unsigned qa[2][4][4];
#pragma unroll
    for (int u = 0; u < 2; ++u) {
        const unsigned* q0 = (const unsigned*)Q + (size_t)(b * M_ + mtile * 128 + mb + u * 16 + g) * 512 + h * 32;
        const unsigned* q1 = (const unsigned*)Q + (size_t)(b * M_ + mtile * 128 + mb + u * 16 + g + 8) * 512 + h * 32;
#pragma unroll
        for (int kk = 0; kk < 4; ++kk) {
            qa[u][kk][0] = q0[kk * 8 + t];
            qa[u][kk][1] = q1[kk * 8 + t];
            qa[u][kk][2] = q0[kk * 8 + 4 + t];
            qa[u][kk][3] = q1[kk * 8 + 4 + t];
        }
    }

    float mS[2][2], lS[2][2];
#pragma unroll
    for (int u = 0; u < 2; ++u) { mS[u][0] = M_INIT; mS[u][1] = M_INIT; lS[u][0] = 0.f; lS[u][1] = 0.f; }
    float o[2][8][4];
#pragma unroll
    for (int u = 0; u < 2; ++u)
#pragma unroll
        for (int i = 0; i < 8; ++i)
#pragma unroll
            for (int j = 0; j < 4; ++j) o[u][i][j] = 0.f;

    const int NT = N_ / 64;  // 32
    for (int kt = 0; kt < NT; ++kt) {
        const int cur = kt & 1;
        // prefetch K/V(kt+1) into other stage
        if (kt + 1 < NT) {
            const unsigned* ks = Kbase + (size_t)(kt + 1) * KV_WORDS + ld;
            const unsigned* vs = Vbase + (size_t)(kt + 1) * KV_WORDS + ld;
            unsigned* kd = Kr + (cur ^ 1) * KV_WORDS + ld;
            unsigned* vd = Vr + (cur ^ 1) * KV_WORDS + ld;
#pragma unroll
            for (int i = 0; i < 4; ++i) cpasync16(kd + i * 4, ks + i * 4);
#pragma unroll
            for (int i = 0; i < 4; ++i) cpasync16(vd + i * 4, vs + i * 4);
            CP_COMMIT();
        }
        if (tid < 64)
            mbias[tid] = g_mask[b * N_ + kt * 64 + tid] ? MASK_BIAS : 0.f;
        if (kt + 1 < NT) CP_WAIT1(); else CP_WAIT0();
        __syncthreads();    // tile kt + mbias visible

        const unsigned* Kc = Kr + cur * KV_WORDS;
        const unsigned* Vc = Vr + cur * KV_WORDS;

        // S = Q K^T — fp16 k16: one LDS.128 feeds 4 MMAs
        float s[2][8][4];
#pragma unroll
        for (int u = 0; u < 2; ++u)
#pragma unroll
            for (int i = 0; i < 8; ++i)
#pragma unroll
                for (int j = 0; j < 4; ++j) s[u][i][j] = 0.f;

#pragma unroll
        for (int kk = 0; kk < 4; ++kk) {
#pragma unroll
            for (int ntp = 0; ntp < 4; ++ntp) {
                uint4 bv = *(const uint4*)(Kc + ((kk * 4 + ntp) * 32 + lane) * 4);
                mma16(s[0][2 * ntp],     qa[0][kk], bv.x, bv.y);
                mma16(s[1][2 * ntp],     qa[1][kk], bv.x, bv.y);
                mma16(s[0][2 * ntp + 1], qa[0][kk], bv.z, bv.w);
                mma16(s[1][2 * ntp + 1], qa[1][kk], bv.z, bv.w);
            }
        }

        // online softmax (base-2), independent per m-tile
#pragma unroll
        for (int u = 0; u < 2; ++u) {
            float mx0 = -3.0e38f, mx1 = -3.0e38f;
#pragma unroll
            for (int nt = 0; nt < 8; ++nt) {
                float b0 = mbias[nt * 8 + 2 * t];
                float b1 = mbias[nt * 8 + 2 * t + 1];
                s[u][nt][0] += b0; s[u][nt][1] += b1;
                s[u][nt][2] += b0; s[u][nt][3] += b1;
                mx0 = fmaxf(mx0, fmaxf(s[u][nt][0], s[u][nt][1]));
                mx1 = fmaxf(mx1, fmaxf(s[u][nt][2], s[u][nt][3]));
            }
            mx0 = fmaxf(mx0, __shfl_xor_sync(0xFFFFFFFFu, mx0, 1));
            mx0 = fmaxf(mx0, __shfl_xor_sync(0xFFFFFFFFu, mx0, 2));
            mx1 = fmaxf(mx1, __shfl_xor_sync(0xFFFFFFFFu, mx1, 1));
            mx1 = fmaxf(mx1, __shfl_xor_sync(0xFFFFFFFFu, mx1, 2));
            float nm0 = fmaxf(mS[u][0], mx0), nm1 = fmaxf(mS[u][1], mx1);
            float cr0 = ex2(mS[u][0] - nm0), cr1 = ex2(mS[u][1] - nm1);
            mS[u][0] = nm0; mS[u][1] = nm1;

            float rs0 = 0.f, rs1 = 0.f;
#pragma unroll
            for (int nt = 0; nt < 8; ++nt) {
                s[u][nt][0] = ex2(s[u][nt][0] - nm0);
                s[u][nt][1] = ex2(s[u][nt][1] - nm0);
                s[u][nt][2] = ex2(s[u][nt][2] - nm1);
                s[u][nt][3] = ex2(s[u][nt][3] - nm1);
                rs0 += s[u][nt][0] + s[u][nt][1];
                rs1 += s[u][nt][2] + s[u][nt][3];
                o[u][nt][0] *= cr0; o[u][nt][1] *= cr0;
                o[u][nt][2] *= cr1; o[u][nt][3] *= cr1;
            }
            lS[u][0] = lS[u][0] * cr0 + rs0;
            lS[u][1] = lS[u][1] * cr1 + rs1;
        }

        // O += P V — P a-fragments pack directly from S c-fragments (no shfl)
#pragma unroll
        for (int kk2 = 0; kk2 < 4; ++kk2) {
            unsigned a[2][4];
#pragma unroll
            for (int u = 0; u < 2; ++u) {
                a[u][0] = h2pack(s[u][2 * kk2][0],     s[u][2 * kk2][1]);
                a[u][1] = h2pack(s[u][2 * kk2][2],     s[u][2 * kk2][3]);
                a[u][2] = h2pack(s[u][2 * kk2 + 1][0], s[u][2 * kk2 + 1][1]);
                a[u][3] = h2pack(s[u][2 * kk2 + 1][2], s[u][2 * kk2 + 1][3]);
            }
#pragma unroll
            for (int ntp = 0; ntp < 4; ++ntp) {
                uint4 bv = *(const uint4*)(Vc + ((kk2 * 4 + ntp) * 32 + lane) * 4);
                mma16(o[0][2 * ntp],     a[0], bv.x, bv.y);
                mma16(o[1][2 * ntp],     a[1], bv.x, bv.y);
                mma16(o[0][2 * ntp + 1], a[0], bv.z, bv.w);
                mma16(o[1][2 * ntp + 1], a[1], bv.z, bv.w);
            }
        }
        __syncthreads();    // stage fully consumed before reuse
    }

    // finalize both m-tiles (g_C: tf32-rounded fp32, consumed by O-projection)
#pragma unroll
    for (int u = 0; u < 2; ++u) {
        float l0 = lS[u][0], l1 = lS[u][1];
        l0 += __shfl_xor_sync(0xFFFFFFFFu, l0, 1);
        l0 += __shfl_xor_sync(0xFFFFFFFFu, l0, 2);
        l1 += __shfl_xor_sync(0xFFFFFFFFu, l1, 1);
        l1 += __shfl_xor_sync(0xFFFFFFFFu, l1, 2);
        float inv0 = 1.f / l0, inv1 = 1.f / l1;

        const int gr0 = mtile * 128 + mb + u * 16 + g;
        const int gr1 = gr0 + 8;
#pragma unroll
        for (int nt = 0; nt < 8; ++nt) {
            int col = h * DH_ + nt * 8 + 2 * t;
            *(float2*)(Cout + ((size_t)(b * M_ + gr0)) * D_ + col) =
                make_float2(__uint_as_float(f2tf(o[u][nt][0] * inv0)),
                            __uint_as_float(f2tf(o[u][nt][1] * inv0)));
            *(float2*)(Cout + ((size_t)(b * M_ + gr1)) * D_ + col) =
                make_float2(__uint_as_float(f2tf(o[u][nt][2] * inv1)),
                            __uint_as_float(f2tf(o[u][nt][3] * inv1)));
        }
    }
}

// ---------------------------------------------------------------------------
// Launch. Inputs: query, key_value, key_padding_mask, W_Q, W_K, W_V, W_O
// ---------------------------------------------------------------------------
extern "C" void kernel_launch(void* const* d_in, const int* in_sizes, int n_in,
                              void* d_out, int out_size)
{
    const float* query = (const float*)d_in[0];
    const float* keyv  = (const float*)d_in[1];
    const unsigned char* mask_raw = (const unsigned char*)d_in[2];
    const float* W_Q = (const float*)d_in[3];
    const float* W_K = (const float*)d_in[4];
    const float* W_V = (const float*)d_in[5];
    const float* W_O = (const float*)d_in[6];
    float* out = (float*)d_out;

    float *gQ, *gK, *gV, *gC;
    cudaGetSymbolAddress((void**)&gQ, g_Q);
    cudaGetSymbolAddress((void**)&gK, g_K);
    cudaGetSymbolAddress((void**)&gV, g_V);
    cudaGetSymbolAddress((void**)&gC, g_C);

    cudaFuncSetAttribute(attn_tc, cudaFuncAttributeMaxDynamicSharedMemorySize,
                         ATT_WORDS * 4);

    mask_expand_kernel<<<1, 1024>>>(mask_raw);

    // one-time tf32 pre-rounding of GEMM operands
    {
        const size_t total4 = (2 * NIN + 4 * NW) / 4;
        int blocks = (int)((total4 + 255) / 256);
        preround_kernel<<<blocks, 256>>>(query, keyv, W_Q, W_K, W_V, W_O);
    }

    dim3 gqkv(D_ / 128, (B_ * M_) / 128, 3);
    gemm_qkv<<<gqkv, 256>>>();

    dim3 gattn(M_ / 128, NH_, B_);
    attn_tc<<<gattn, 128, ATT_WORDS * 4>>>(gQ, gK, gV, gC);

    dim3 gout(D_ / 128, (B_ * M_) / 128);
    gemm_out<<<gout, 256>>>(out);
}

// round 15
// speedup vs baseline: 1.5603x; 1.0750x over previous
#include <cuda_runtime.h>
#include <cuda_fp16.h>
#include <stdint.h>

#define B_  2
#define M_  2048
#define N_  2048
#define D_  1024
#define NH_ 16
#define DH_ 64

#define NIN ((size_t)B_ * M_ * D_)   // 4M elems
#define NW  ((size_t)D_ * D_)        // 1M elems

// Scratch (device globals: no allocation allowed).
// g_Q: fp16(Q*scale*log2e) row-major. g_K/g_V: fp16 MMA fragment order.
// g_C: fp16 row-major (attention out). g_Xq/g_Xkv: fp16 row-major inputs.
// g_W*: fp16 TRANSPOSED [N,K] weights. (All declared float; used as half.)
__device__ float g_Q[NIN];
__device__ float g_K[NIN];
__device__ float g_V[NIN];
__device__ float g_C[NIN];
__device__ float g_Xq[NIN];
__device__ float g_Xkv[NIN];
__device__ float g_Wq[NW], g_Wk[NW], g_Wv[NW], g_Wo[NW];
__device__ unsigned char g_mask[B_ * N_];

// ---------------------------------------------------------------------------
// helpers
// ---------------------------------------------------------------------------
__device__ __forceinline__ float ex2(float x) {
    float y; asm("ex2.approx.f32 %0, %1;" : "=f"(y) : "f"(x)); return y;
}
// pack two f32 -> f16x2 (lo = first elem)
__device__ __forceinline__ unsigned h2pack(float lo, float hi) {
    unsigned d;
    asm("cvt.rn.f16x2.f32 %0, %1, %2;" : "=r"(d) : "f"(hi), "f"(lo));
    return d;
}
// fp16 m16n8k16
__device__ __forceinline__ void mma16(float* c, const unsigned* a, unsigned b0, unsigned b1) {
    asm volatile(
        "mma.sync.aligned.m16n8k16.row.col.f32.f16.f16.f32 "
        "{%0,%1,%2,%3},{%4,%5,%6,%7},{%8,%9},{%0,%1,%2,%3};\n"
        : "+f"(c[0]), "+f"(c[1]), "+f"(c[2]), "+f"(c[3])
        : "r"(a[0]), "r"(a[1]), "r"(a[2]), "r"(a[3]), "r"(b0), "r"(b1));
}
__device__ __forceinline__ void cpasync16(void* dst, const void* src) {
    unsigned d = (unsigned)__cvta_generic_to_shared(dst);
    asm volatile("cp.async.cg.shared.global [%0], [%1], 16;\n" :: "r"(d), "l"(src));
}
#define CP_COMMIT() asm volatile("cp.async.commit_group;\n" ::: "memory")
#define CP_WAIT0()  asm volatile("cp.async.wait_group 0;\n" ::: "memory")
#define CP_WAIT1()  asm volatile("cp.async.wait_group 1;\n" ::: "memory")

#define SCQ (0.125f * 1.44269504f)   // 1/sqrt(dh) * log2(e), folded into Q

// ---------------------------------------------------------------------------
// fp16 fragment-order indices (R13-proven).
__device__ __forceinline__ size_t kfrag_word(int R, int c) {
    int b = R >> 11, key = R & 2047, kt = key >> 6, ky = key & 63;
    int h = c >> 6, d = c & 63;
    int kk = d >> 4, dd = d & 15;
    int bsel = dd >> 3, tq = (dd & 7) >> 1;
    int nt = ky >> 3, g = ky & 7;
    int lane = g * 4 + tq;
    int ntp = nt >> 1, j = (nt & 1) * 2 + bsel;
    int word = ((kk * 4 + ntp) * 32 + lane) * 4 + j;
    return ((size_t)((b * NH_ + h) * 32 + kt)) * 2048 + word;
}
__device__ __forceinline__ size_t vfrag_half(int R, int c) {
    int b = R >> 11, key = R & 2047, kt = key >> 6, ky = key & 63;
    int h = c >> 6, d = c & 63;
    int kk = ky >> 4, kyd = ky & 15;
    int bsel = kyd >> 3, tq = (kyd & 7) >> 1, hs = kyd & 1;
    int nt = d >> 3, g = d & 7;
    int lane = g * 4 + tq;
    int ntp = nt >> 1, j = (nt & 1) * 2 + bsel;
    int word = ((kk * 4 + ntp) * 32 + lane) * 4 + j;
    return ((size_t)((b * NH_ + h) * 32 + kt)) * 4096 + (size_t)word * 2 + hs;
}

// ---------------------------------------------------------------------------
// Mask dtype sniffer + expander (bool may arrive as u8 / i32 / f32)
// ---------------------------------------------------------------------------
__global__ void mask_expand_kernel(const unsigned char* __restrict__ raw) {
    __shared__ int s_not_int, s_not_float;
    if (threadIdx.x == 0) { s_not_int = 0; s_not_float = 0; }
    __syncthreads();
    const unsigned int* w = (const unsigned int*)raw;
    for (int i = threadIdx.x; i < 1024; i += blockDim.x) {
        unsigned int x = w[i];
        if (x != 0u && x != 1u)          atomicOr(&s_not_int, 1);
        if (x != 0u && x != 0x3F800000u) atomicOr(&s_not_float, 1);
    }
    __syncthreads();
    int mode = (!s_not_int) ? 0 : ((!s_not_float) ? 1 : 2);
    if (mode == 2) {
        for (int i = threadIdx.x; i < B_ * N_; i += blockDim.x)
            g_mask[i] = raw[i] ? 1 : 0;
    } else {
        for (int i = threadIdx.x; i < B_ * N_; i += blockDim.x)
            g_mask[i] = w[i] ? 1 : 0;
    }
}

// ---------------------------------------------------------------------------
// One-time fp16 conversion: inputs -> fp16 row-major; weights -> fp16
// TRANSPOSED [N,K] row-major.
// ---------------------------------------------------------------------------
__global__ __launch_bounds__(256) void preround_kernel(
    const float* __restrict__ q, const float* __restrict__ kv,
    const float* __restrict__ wq, const float* __restrict__ wk,
    const float* __restrict__ wv, const float* __restrict__ wo)
{
    size_t i4 = (size_t)blockIdx.x * blockDim.x + threadIdx.x;
    const size_t total4 = (2 * NIN + 4 * NW) / 4;
    if (i4 >= total4) return;
    size_t off = i4 * 4;
    if (off < 2 * NIN) {
        const float* src; float* dst;
        if (off < NIN) { src = q; dst = g_Xq; }
        else           { src = kv; dst = g_Xkv; off -= NIN; }
        float4 v = *(const float4*)(src + off);
        unsigned* d = (unsigned*)dst;
        d[(off >> 1)]     = h2pack(v.x, v.y);
        d[(off >> 1) + 1] = h2pack(v.z, v.w);
    } else {
        off -= 2 * NIN;
        const float* src; float* dst;
        if (off < NW)                { src = wq; dst = g_Wq; }
        else if ((off -= NW) < NW)   { src = wk; dst = g_Wk; }
        else if ((off -= NW) < NW)   { src = wv; dst = g_Wv; }
        else        { off -= NW;       src = wo; dst = g_Wo; }
        float4 v = *(const float4*)(src + off);
        int k = (int)(off >> 10), n = (int)(off & 1023);
        __half* dh = (__half*)dst;
        dh[(size_t)(n + 0) * D_ + k] = __float2half_rn(v.x);
        dh[(size_t)(n + 1) * D_ + k] = __float2half_rn(v.y);
        dh[(size_t)(n + 2) * D_ + k] = __float2half_rn(v.z);
        dh[(size_t)(n + 3) * D_ + k] = __float2half_rn(v.w);
    }
}

// ---------------------------------------------------------------------------
// FP16 GEMM: C[M,N] = A[M,K] @ Bt[N,K]^T. A fp16 row-major, Bt fp16 [N,K]
// row-major (pre-transposed). 128x128 tile, BK=32, m16n8k16, cp.async
// 2-stage, 256 thr, (256,2). Smem rows padded to 20 words.
// Loader: 2 threads/row, thread (tid&1) covers words [lw, lw+8), lw = 8*(tid&1).
// Epilogue MODE: 0 = fp32 row-major, 2 = fp16(acc*SCQ) row-major,
//                3 = fp16 K fragment order, 4 = fp16 V fragment order.
// ---------------------------------------------------------------------------
#define GSTR 20                          // words per 32-half row (16 + 4 pad)
#define GT_WORDS (128 * GSTR)            // 2560 words per tile

template<int MODE>
__device__ __forceinline__ void gemm_body(
    const __half* __restrict__ A, const __half* __restrict__ Bt, float* __restrict__ C)
{
    __shared__ unsigned As[2][GT_WORDS];
    __shared__ unsigned Bs[2][GT_WORDS];

    const int tid  = threadIdx.x;
    const int warp = tid >> 5, lane = tid & 31;
    const int g = lane >> 2, t = lane & 3;
    const int wm = (warp >> 2) * 64;
    const int wn = (warp & 3) * 32;
    const int rowBase = blockIdx.y * 128;
    const int colBase = blockIdx.x * 128;
    const int lr = tid >> 1;             // loader row 0..127
    const int lw = (tid & 1) * 8;        // loader WORD offset: 0 or 8
    const int lh = lw * 2;               // loader half offset: 0 or 16

    float acc[4][4][4];
#pragma unroll
    for (int i = 0; i < 4; ++i)
#pragma unroll
        for (int j = 0; j < 4; ++j)
#pragma unroll
            for (int k = 0; k < 4; ++k) acc[i][j][k] = 0.f;

    // stage 0 load: each thread covers 8 words (16 halves) of its row
    {
        cpasync16(As[0] + lr * GSTR + lw,     A + (size_t)(rowBase + lr) * D_ + lh);
        cpasync16(As[0] + lr * GSTR + lw + 4, A + (size_t)(rowBase + lr) * D_ + lh + 8);
        cpasync16(Bs[0] + lr * GSTR + lw,     Bt + (size_t)(colBase + lr) * D_ + lh);
        cpasync16(Bs[0] + lr * GSTR + lw + 4, Bt + (size_t)(colBase + lr) * D_ + lh + 8);
    }
    CP_COMMIT();

    const int NIT = D_ / 32;   // 32
    for (int it = 0; it < NIT; ++it) {
        const int cur = it & 1;
        if (it + 1 < NIT) {
            const int k0 = (it + 1) * 32;
            cpasync16(As[cur ^ 1] + lr * GSTR + lw,     A + (size_t)(rowBase + lr) * D_ + k0 + lh);
            cpasync16(As[cur ^ 1] + lr * GSTR + lw + 4, A + (size_t)(rowBase + lr) * D_ + k0 + lh + 8);
            cpasync16(Bs[cur ^ 1] + lr * GSTR + lw,     Bt + (size_t)(colBase + lr) * D_ + k0 + lh);
            cpasync16(Bs[cur ^ 1] + lr * GSTR + lw + 4, Bt + (size_t)(colBase + lr) * D_ + k0 + lh + 8);
            CP_COMMIT();
            CP_WAIT1();
        } else {
            CP_WAIT0();
        }
        __syncthreads();

        const unsigned* Ac = As[cur];
        const unsigned* Bc = Bs[cur];
#pragma unroll
        for (int kk = 0; kk < 2; ++kk) {
            const int kb = kk * 8;
            unsigned a[4][4], bf[4][2];
#pragma unroll
            for (int mt = 0; mt < 4; ++mt) {
                int mr = wm + mt * 16;
                a[mt][0] = Ac[(mr + g) * GSTR + kb + t];
                a[mt][1] = Ac[(mr + g + 8) * GSTR + kb + t];
                a[mt][2] = Ac[(mr + g) * GSTR + kb + t + 4];
                a[mt][3] = Ac[(mr + g + 8) * GSTR + kb + t + 4];
            }
#pragma unroll
            for (int nt = 0; nt < 4; ++nt) {
                int nc = wn + nt * 8 + g;
                bf[nt][0] = Bc[nc * GSTR + kb + t];
                bf[nt][1] = Bc[nc * GSTR + kb + t + 4];
            }
#pragma unroll
            for (int mt = 0; mt < 4; ++mt)
#pragma unroll
                for (int nt = 0; nt < 4; ++nt)
                    mma16(acc[mt][nt], a[mt], bf[nt][0], bf[nt][1]);
        }
        __syncthreads();
    }

#pragma unroll
    for (int mt = 0; mt < 4; ++mt) {
        int r0 = rowBase + wm + mt * 16 + g;
#pragma unroll
        for (int nt = 0; nt < 4; ++nt) {
            int c0 = colBase + wn + nt * 8 + 2 * t;
            float v0 = acc[mt][nt][0], v1 = acc[mt][nt][1];
            float v2 = acc[mt][nt][2], v3 = acc[mt][nt][3];
            if (MODE == 0) {
                *(float2*)(C + (size_t)r0 * D_ + c0)       = make_float2(v0, v1);
                *(float2*)(C + (size_t)(r0 + 8) * D_ + c0) = make_float2(v2, v3);
            } else if (MODE == 2) {
                unsigned* Ch = (unsigned*)C;
                Ch[((size_t)r0 * D_ + c0) >> 1]       = h2pack(v0 * SCQ, v1 * SCQ);
                Ch[((size_t)(r0 + 8) * D_ + c0) >> 1] = h2pack(v2 * SCQ, v3 * SCQ);
            } else if (MODE == 3) {
                unsigned* Ch = (unsigned*)C;
                Ch[kfrag_word(r0, c0)]     = h2pack(v0, v1);
                Ch[kfrag_word(r0 + 8, c0)] = h2pack(v2, v3);
            } else {  // MODE 4
                __half* Chh = (__half*)C;
                Chh[vfrag_half(r0,     c0)]     = __float2half_rn(v0);
                Chh[vfrag_half(r0,     c0 + 1)] = __float2half_rn(v1);
                Chh[vfrag_half(r0 + 8, c0)]     = __float2half_rn(v2);
                Chh[vfrag_half(r0 + 8, c0 + 1)] = __float2half_rn(v3);
            }
        }
    }
}

__global__ __launch_bounds__(256, 2) void gemm_qkv()
{
    if (blockIdx.z == 0)      gemm_body<2>((const __half*)g_Xq,  (const __half*)g_Wq, g_Q);
    else if (blockIdx.z == 1) gemm_body<3>((const __half*)g_Xkv, (const __half*)g_Wk, g_K);
    else                      gemm_body<4>((const __half*)g_Xkv, (const __half*)g_Wv, g_V);
}

__global__ __launch_bounds__(256, 2) void gemm_out(float* __restrict__ out)
{
    gemm_body<0>((const __half*)g_C, (const __half*)g_Wo, out);
}

// ---------------------------------------------------------------------------
// FP16 flash attention (R13-proven): 2 m-tiles/warp, Q in registers, P packs
// from S c-fragments, K+V double-buffered cp.async. Epilogue writes fp16 g_C.
// Block = 128 rows, 4 warps. Grid: (M/128, NH, B). Smem 33KB, (128,2).
// ---------------------------------------------------------------------------
#define KV_WORDS 2048
#define AK_OFF 0
#define AV_OFF (2 * KV_WORDS)
#define AMB_OFF (AV_OFF + 2 * KV_WORDS)
#define ATT_WORDS (AMB_OFF + 64)

#define M_INIT (-1.0e4f)
#define MASK_BIAS (-1.0e9f)

__global__ __launch_bounds__(128, 2) void attn_tc(
    const float* __restrict__ Q, const float* __restrict__ K,
    const float* __restrict__ V, float* __restrict__ Cout)
{
    extern __shared__ unsigned smemu[];
    unsigned* Kr = smemu + AK_OFF;
    unsigned* Vr = smemu + AV_OFF;
    float* mbias = (float*)(smemu + AMB_OFF);

    const int mtile = blockIdx.x, h = blockIdx.y, b = blockIdx.z;
    const int tid = threadIdx.x;
    const int warp = tid >> 5, lane = tid & 31;
    const int g = lane >> 2, t = lane & 3;
    const int mb = warp * 32;

    const size_t tilebase = ((size_t)(b * NH_ + h) * 32) * KV_WORDS;
    const unsigned* Kbase = (const unsigned*)K + tilebase;
    const unsigned* Vbase = (const unsigned*)V + tilebase;
    const int ld = tid * 16;

    {
#pragma unroll
        for (int i = 0; i < 4; ++i) cpasync16(Kr + ld + i * 4, Kbase + ld + i * 4);
#pragma unroll
        for (int i = 0; i < 4; ++i) cpasync16(Vr + ld + i * 4, Vbase + ld + i * 4);
    }
    CP_COMMIT();

    unsigned qa[2][4][4];
#pragma unroll
    for (int u = 0; u < 2; ++u) {
        const unsigned* q0 = (const unsigned*)Q + (size_t)(b * M_ + mtile * 128 + mb + u * 16 + g) * 512 + h * 32;
        const unsigned* q1 = (const unsigned*)Q + (size_t)(b * M_ + mtile * 128 + mb + u * 16 + g + 8) * 512 + h * 32;
#pragma unroll
        for (int kk = 0; kk < 4; ++kk) {
            qa[u][kk][0] = q0[kk * 8 + t];
            qa[u][kk][1] = q1[kk * 8 + t];
            qa[u][kk][2] = q0[kk * 8 + 4 + t];
            qa[u][kk][3] = q1[kk * 8 + 4 + t];
        }
    }

    float mS[2][2], lS[2][2];
#pragma unroll
    for (int u = 0; u < 2; ++u) { mS[u][0] = M_INIT; mS[u][1] = M_INIT; lS[u][0] = 0.f; lS[u][1] = 0.f; }
    float o[2][8][4];
#pragma unroll
    for (int u = 0; u < 2; ++u)
#pragma unroll
        for (int i = 0; i < 8; ++i)
#pragma unroll
            for (int j = 0; j < 4; ++j) o[u][i][j] = 0.f;

    const int NT = N_ / 64;  // 32
    for (int kt = 0; kt < NT; ++kt) {
        const int cur = kt & 1;
        if (kt + 1 < NT) {
            const unsigned* ks = Kbase + (size_t)(kt + 1) * KV_WORDS + ld;
            const unsigned* vs = Vbase + (size_t)(kt + 1) * KV_WORDS + ld;
            unsigned* kd = Kr + (cur ^ 1) * KV_WORDS + ld;
            unsigned* vd = Vr + (cur ^ 1) * KV_WORDS + ld;
#pragma unroll
            for (int i = 0; i < 4; ++i) cpasync16(kd + i * 4, ks + i * 4);
#pragma unroll
            for (int i = 0; i < 4; ++i) cpasync16(vd + i * 4, vs + i * 4);
            CP_COMMIT();
        }
        if (tid < 64)
            mbias[tid] = g_mask[b * N_ + kt * 64 + tid] ? MASK_BIAS : 0.f;
        if (kt + 1 < NT) CP_WAIT1(); else CP_WAIT0();
        __syncthreads();

        const unsigned* Kc = Kr + cur * KV_WORDS;
        const unsigned* Vc = Vr + cur * KV_WORDS;

        float s[2][8][4];
#pragma unroll
        for (int u = 0; u < 2; ++u)
#pragma unroll
            for (int i = 0; i < 8; ++i)
#pragma unroll
                for (int j = 0; j < 4; ++j) s[u][i][j] = 0.f;

#pragma unroll
        for (int kk = 0; kk < 4; ++kk) {
#pragma unroll
            for (int ntp = 0; ntp < 4; ++ntp) {
                uint4 bv = *(const uint4*)(Kc + ((kk * 4 + ntp) * 32 + lane) * 4);
                mma16(s[0][2 * ntp],     qa[0][kk], bv.x, bv.y);
                mma16(s[1][2 * ntp],     qa[1][kk], bv.x, bv.y);
                mma16(s[0][2 * ntp + 1], qa[0][kk], bv.z, bv.w);
                mma16(s[1][2 * ntp + 1], qa[1][kk], bv.z, bv.w);
            }
        }

#pragma unroll
        for (int u = 0; u < 2; ++u) {
            float mx0 = -3.0e38f, mx1 = -3.0e38f;
#pragma unroll
            for (int nt = 0; nt < 8; ++nt) {
                float b0 = mbias[nt * 8 + 2 * t];
                float b1 = mbias[nt * 8 + 2 * t + 1];
                s[u][nt][0] += b0; s[u][nt][1] += b1;
                s[u][nt][2] += b0; s[u][nt][3] += b1;
                mx0 = fmaxf(mx0, fmaxf(s[u][nt][0], s[u][nt][1]));
                mx1 = fmaxf(mx1, fmaxf(s[u][nt][2], s[u][nt][3]));
            }
            mx0 = fmaxf(mx0, __shfl_xor_sync(0xFFFFFFFFu, mx0, 1));
            mx0 = fmaxf(mx0, __shfl_xor_sync(0xFFFFFFFFu, mx0, 2));
            mx1 = fmaxf(mx1, __shfl_xor_sync(0xFFFFFFFFu, mx1, 1));
            mx1 = fmaxf(mx1, __shfl_xor_sync(0xFFFFFFFFu, mx1, 2));
            float nm0 = fmaxf(mS[u][0], mx0), nm1 = fmaxf(mS[u][1], mx1);
            float cr0 = ex2(mS[u][0] - nm0), cr1 = ex2(mS[u][1] - nm1);
            mS[u][0] = nm0; mS[u][1] = nm1;

            float rs0 = 0.f, rs1 = 0.f;
#pragma unroll
            for (int nt = 0; nt < 8; ++nt) {
                s[u][nt][0] = ex2(s[u][nt][0] - nm0);
                s[u][nt][1] = ex2(s[u][nt][1] - nm0);
                s[u][nt][2] = ex2(s[u][nt][2] - nm1);
                s[u][nt][3] = ex2(s[u][nt][3] - nm1);
                rs0 += s[u][nt][0] + s[u][nt][1];
                rs1 += s[u][nt][2] + s[u][nt][3];
                o[u][nt][0] *= cr0; o[u][nt][1] *= cr0;
                o[u][nt][2] *= cr1; o[u][nt][3] *= cr1;
            }
            lS[u][0] = lS[u][0] * cr0 + rs0;
            lS[u][1] = lS[u][1] * cr1 + rs1;
        }

#pragma unroll
        for (int kk2 = 0; kk2 < 4; ++kk2) {
            unsigned a[2][4];
#pragma unroll
            for (int u = 0; u < 2; ++u) {
                a[u][0] = h2pack(s[u][2 * kk2][0],     s[u][2 * kk2][1]);
                a[u][1] = h2pack(s[u][2 * kk2][2],     s[u][2 * kk2][3]);
                a[u][2] = h2pack(s[u][2 * kk2 + 1][0], s[u][2 * kk2 + 1][1]);
                a[u][3] = h2pack(s[u][2 * kk2 + 1][2], s[u][2 * kk2 + 1][3]);
            }
#pragma unroll
            for (int ntp = 0; ntp < 4; ++ntp) {
                uint4 bv = *(const uint4*)(Vc + ((kk2 * 4 + ntp) * 32 + lane) * 4);
                mma16(o[0][2 * ntp],     a[0], bv.x, bv.y);
                mma16(o[1][2 * ntp],     a[1], bv.x, bv.y);
                mma16(o[0][2 * ntp + 1], a[0], bv.z, bv.w);
                mma16(o[1][2 * ntp + 1], a[1], bv.z, bv.w);
            }
        }
        __syncthreads();
    }

    // finalize: write fp16 row-major g_C (A of the O-projection)
#pragma unroll
    for (int u = 0; u < 2; ++u) {
        float l0 = lS[u][0], l1 = lS[u][1];
        l0 += __shfl_xor_sync(0xFFFFFFFFu, l0, 1);
        l0 += __shfl_xor_sync(0xFFFFFFFFu, l0, 2);
        l1 += __shfl_xor_sync(0xFFFFFFFFu, l1, 1);
        l1 += __shfl_xor_sync(0xFFFFFFFFu, l1, 2);
        float inv0 = 1.f / l0, inv1 = 1.f / l1;

        const int gr0 = mtile * 128 + mb + u * 16 + g;
        const int gr1 = gr0 + 8;
        unsigned* Ch = (unsigned*)Cout;
#pragma unroll
        for (int nt = 0; nt < 8; ++nt) {
            int col = h * DH_ + nt * 8 + 2 * t;
            Ch[((size_t)(b * M_ + gr0) * D_ + col) >> 1] =
                h2pack(o[u][nt][0] * inv0, o[u][nt][1] * inv0);
            Ch[((size_t)(b * M_ + gr1) * D_ + col) >> 1] =
                h2pack(o[u][nt][2] * inv1, o[u][nt][3] * inv1);
        }
    }
}

// ---------------------------------------------------------------------------
// Launch. Inputs: query, key_value, key_padding_mask, W_Q, W_K, W_V, W_O
// ---------------------------------------------------------------------------
extern "C" void kernel_launch(void* const* d_in, const int* in_sizes, int n_in,
                              void* d_out, int out_size)
{
    const float* query = (const float*)d_in[0];
    const float* keyv  = (const float*)d_in[1];
    const unsigned char* mask_raw = (const unsigned char*)d_in[2];
    const float* W_Q = (const float*)d_in[3];
    const float* W_K = (const float*)d_in[4];
    const float* W_V = (const float*)d_in[5];
    const float* W_O = (const float*)d_in[6];
    float* out = (float*)d_out;

    float *gQ, *gK, *gV, *gC;
    cudaGetSymbolAddress((void**)&gQ, g_Q);
    cudaGetSymbolAddress((void**)&gK, g_K);
    cudaGetSymbolAddress((void**)&gV, g_V);
    cudaGetSymbolAddress((void**)&gC, g_C);

    cudaFuncSetAttribute(attn_tc, cudaFuncAttributeMaxDynamicSharedMemorySize,
                         ATT_WORDS * 4);

    mask_expand_kernel<<<1, 1024>>>(mask_raw);

    // one-time fp16 conversion (+weight transpose)
    {
        const size_t total4 = (2 * NIN + 4 * NW) / 4;
        int blocks = (int)((total4 + 255) / 256);
        preround_kernel<<<blocks, 256>>>(query, keyv, W_Q, W_K, W_V, W_O);
    }

    dim3 gqkv(D_ / 128, (B_ * M_) / 128, 3);
    gemm_qkv<<<gqkv, 256>>>();

    dim3 gattn(M_ / 128, NH_, B_);
    attn_tc<<<gattn, 128, ATT_WORDS * 4>>>(gQ, gK, gV, gC);

    dim3 gout(D_ / 128, (B_ * M_) / 128);
    gemm_out<<<gout, 256>>>(out);
}

// round 16
// speedup vs baseline: 1.7215x; 1.1033x over previous
#include <cuda_runtime.h>
#include <cuda_fp16.h>
#include <stdint.h>

#define B_  2
#define M_  2048
#define N_  2048
#define D_  1024
#define NH_ 16
#define DH_ 64

#define NIN ((size_t)B_ * M_ * D_)   // 4M elems
#define NW  ((size_t)D_ * D_)        // 1M elems

// Scratch (device globals: no allocation allowed).
// g_Q: fp16(Q*scale*log2e) row-major. g_K/g_V: fp16 MMA fragment order.
// g_C: fp16 row-major (attention out). g_Xq/g_Xkv: fp16 row-major inputs.
// g_W*: fp16 TRANSPOSED [N,K] weights. (Declared float; used as half.)
__device__ float g_Q[NIN];
__device__ float g_K[NIN];
__device__ float g_V[NIN];
__device__ float g_C[NIN];
__device__ float g_Xq[NIN];
__device__ float g_Xkv[NIN];
__device__ float g_Wq[NW], g_Wk[NW], g_Wv[NW], g_Wo[NW];
__device__ unsigned char g_mask[B_ * N_];

// ---------------------------------------------------------------------------
// helpers
// ---------------------------------------------------------------------------
__device__ __forceinline__ float ex2(float x) {
    float y; asm("ex2.approx.f32 %0, %1;" : "=f"(y) : "f"(x)); return y;
}
__device__ __forceinline__ unsigned h2pack(float lo, float hi) {
    unsigned d;
    asm("cvt.rn.f16x2.f32 %0, %1, %2;" : "=r"(d) : "f"(hi), "f"(lo));
    return d;
}
__device__ __forceinline__ void mma16(float* c, const unsigned* a, unsigned b0, unsigned b1) {
    asm volatile(
        "mma.sync.aligned.m16n8k16.row.col.f32.f16.f16.f32 "
        "{%0,%1,%2,%3},{%4,%5,%6,%7},{%8,%9},{%0,%1,%2,%3};\n"
        : "+f"(c[0]), "+f"(c[1]), "+f"(c[2]), "+f"(c[3])
        : "r"(a[0]), "r"(a[1]), "r"(a[2]), "r"(a[3]), "r"(b0), "r"(b1));
}
__device__ __forceinline__ void ldsm4(unsigned* r, unsigned saddr) {
    asm volatile("ldmatrix.sync.aligned.m8n8.x4.shared.b16 {%0,%1,%2,%3}, [%4];"
                 : "=r"(r[0]), "=r"(r[1]), "=r"(r[2]), "=r"(r[3]) : "r"(saddr));
}
__device__ __forceinline__ void cpasync16(void* dst, const void* src) {
    unsigned d = (unsigned)__cvta_generic_to_shared(dst);
    asm volatile("cp.async.cg.shared.global [%0], [%1], 16;\n" :: "r"(d), "l"(src));
}
#define CP_COMMIT() asm volatile("cp.async.commit_group;\n" ::: "memory")
#define CP_WAIT0()  asm volatile("cp.async.wait_group 0;\n" ::: "memory")
#define CP_WAIT1()  asm volatile("cp.async.wait_group 1;\n" ::: "memory")

#define SCQ (0.125f * 1.44269504f)   // 1/sqrt(dh) * log2(e), folded into Q

// ---------------------------------------------------------------------------
// fp16 fragment-order indices (R13-proven).
__device__ __forceinline__ size_t kfrag_word(int R, int c) {
    int b = R >> 11, key = R & 2047, kt = key >> 6, ky = key & 63;
    int h = c >> 6, d = c & 63;
    int kk = d >> 4, dd = d & 15;
    int bsel = dd >> 3, tq = (dd & 7) >> 1;
    int nt = ky >> 3, g = ky & 7;
    int lane = g * 4 + tq;
    int ntp = nt >> 1, j = (nt & 1) * 2 + bsel;
    int word = ((kk * 4 + ntp) * 32 + lane) * 4 + j;
    return ((size_t)((b * NH_ + h) * 32 + kt)) * 2048 + word;
}
__device__ __forceinline__ size_t vfrag_half(int R, int c) {
    int b = R >> 11, key = R & 2047, kt = key >> 6, ky = key & 63;
    int h = c >> 6, d = c & 63;
    int kk = ky >> 4, kyd = ky & 15;
    int bsel = kyd >> 3, tq = (kyd & 7) >> 1, hs = kyd & 1;
    int nt = d >> 3, g = d & 7;
    int lane = g * 4 + tq;
    int ntp = nt >> 1, j = (nt & 1) * 2 + bsel;
    int word = ((kk * 4 + ntp) * 32 + lane) * 4 + j;
    return ((size_t)((b * NH_ + h) * 32 + kt)) * 4096 + (size_t)word * 2 + hs;
}

// ---------------------------------------------------------------------------
// Mask dtype sniffer + expander (bool may arrive as u8 / i32 / f32)
// ---------------------------------------------------------------------------
__global__ void mask_expand_kernel(const unsigned char* __restrict__ raw) {
    __shared__ int s_not_int, s_not_float;
    if (threadIdx.x == 0) { s_not_int = 0; s_not_float = 0; }
    __syncthreads();
    const unsigned int* w = (const unsigned int*)raw;
    for (int i = threadIdx.x; i < 1024; i += blockDim.x) {
        unsigned int x = w[i];
        if (x != 0u && x != 1u)          atomicOr(&s_not_int, 1);
        if (x != 0u && x != 0x3F800000u) atomicOr(&s_not_float, 1);
    }
    __syncthreads();
    int mode = (!s_not_int) ? 0 : ((!s_not_float) ? 1 : 2);
    if (mode == 2) {
        for (int i = threadIdx.x; i < B_ * N_; i += blockDim.x)
            g_mask[i] = raw[i] ? 1 : 0;
    } else {
        for (int i = threadIdx.x; i < B_ * N_; i += blockDim.x)
            g_mask[i] = w[i] ? 1 : 0;
    }
}

// ---------------------------------------------------------------------------
// One-time fp16 conversion of the two inputs (row-major, vectorized).
// ---------------------------------------------------------------------------
__global__ __launch_bounds__(256) void preround_kernel(
    const float* __restrict__ q, const float* __restrict__ kv)
{
    size_t i4 = (size_t)blockIdx.x * blockDim.x + threadIdx.x;
    const size_t total4 = (2 * NIN) / 4;
    if (i4 >= total4) return;
    size_t off = i4 * 4;
    const float* src; float* dst;
    if (off < NIN) { src = q; dst = g_Xq; }
    else           { src = kv; dst = g_Xkv; off -= NIN; }
    float4 v = *(const float4*)(src + off);
    unsigned* d = (unsigned*)dst;
    d[(off >> 1)]     = h2pack(v.x, v.y);
    d[(off >> 1) + 1] = h2pack(v.z, v.w);
}

// ---------------------------------------------------------------------------
// Weight transpose + fp16 convert: w[K,N] fp32 -> dh[N,K] fp16, coalesced
// both sides via a 32x33 smem tile. Block 32x8, grid (N/32, K/32, 4).
// ---------------------------------------------------------------------------
__global__ __launch_bounds__(256) void wtrans_kernel(
    const float* __restrict__ wq, const float* __restrict__ wk,
    const float* __restrict__ wv, const float* __restrict__ wo)
{
    __shared__ float tile[32][33];
    const float* src;
    float* dstf;
    switch (blockIdx.z) {
        case 0: src = wq; dstf = g_Wq; break;
        case 1: src = wk; dstf = g_Wk; break;
        case 2: src = wv; dstf = g_Wv; break;
        default: src = wo; dstf = g_Wo; break;
    }
    __half* dst = (__half*)dstf;
    const int n0 = blockIdx.x * 32, k0 = blockIdx.y * 32;
    const int tx = threadIdx.x, ty = threadIdx.y;
#pragma unroll
    for (int i = 0; i < 4; ++i)
        tile[ty + 8 * i][tx] = src[(size_t)(k0 + ty + 8 * i) * D_ + n0 + tx];
    __syncthreads();
#pragma unroll
    for (int i = 0; i < 4; ++i)
        dst[(size_t)(n0 + ty + 8 * i) * D_ + k0 + tx] =
            __float2half_rn(tile[tx][ty + 8 * i]);
}

// ---------------------------------------------------------------------------
// FP16 GEMM: C[M,N] = A[M,K] @ Bt[N,K]^T, fragment loads via ldmatrix.x4.
// A fp16 row-major, Bt fp16 [N,K] row-major. 128x128 tile, BK=32, cp.async
// 2-stage, 256 thr, (256,2). Smem rows padded to 20 words (LDSM conflict-free).
// Epilogue MODE: 0 = fp32 row-major, 2 = fp16(acc*SCQ) row-major,
//                3 = fp16 K fragment order, 4 = fp16 V fragment order.
// ---------------------------------------------------------------------------
#define GSTR 20
#define GT_WORDS (128 * GSTR)

template<int MODE>
__device__ __forceinline__ void gemm_body(
    const __half* __restrict__ A, const __half* __restrict__ Bt, float* __restrict__ C)
{
    __shared__ unsigned As[2][GT_WORDS];
    __shared__ unsigned Bs[2][GT_WORDS];

    const int tid  = threadIdx.x;
    const int warp = tid >> 5, lane = tid & 31;
    const int g = lane >> 2, t = lane & 3;
    const int wm = (warp >> 2) * 64;
    const int wn = (warp & 3) * 32;
    const int rowBase = blockIdx.y * 128;
    const int colBase = blockIdx.x * 128;
    const int lr = tid >> 1;             // loader row 0..127
    const int lw = (tid & 1) * 8;        // loader WORD offset
    const int lh = lw * 2;               // loader half offset

    // ldmatrix per-lane address components (word units)
    const int a_row = lane & 15;                       // within m16
    const int a_col = (lane & 16) ? 4 : 0;             // k-half select
    const int b_row = (lane & 7) + ((lane & 16) ? 8 : 0);  // within n16
    const int b_col = (lane & 8) ? 4 : 0;

    float acc[4][4][4];
#pragma unroll
    for (int i = 0; i < 4; ++i)
#pragma unroll
        for (int j = 0; j < 4; ++j)
#pragma unroll
            for (int k = 0; k < 4; ++k) acc[i][j][k] = 0.f;

    {
        cpasync16(As[0] + lr * GSTR + lw,     A + (size_t)(rowBase + lr) * D_ + lh);
        cpasync16(As[0] + lr * GSTR + lw + 4, A + (size_t)(rowBase + lr) * D_ + lh + 8);
        cpasync16(Bs[0] + lr * GSTR + lw,     Bt + (size_t)(colBase + lr) * D_ + lh);
        cpasync16(Bs[0] + lr * GSTR + lw + 4, Bt + (size_t)(colBase + lr) * D_ + lh + 8);
    }
    CP_COMMIT();

    const int NIT = D_ / 32;   // 32
    for (int it = 0; it < NIT; ++it) {
        const int cur = it & 1;
        if (it + 1 < NIT) {
            const int k0 = (it + 1) * 32;
            cpasync16(As[cur ^ 1] + lr * GSTR + lw,     A + (size_t)(rowBase + lr) * D_ + k0 + lh);
            cpasync16(As[cur ^ 1] + lr * GSTR + lw + 4, A + (size_t)(rowBase + lr) * D_ + k0 + lh + 8);
            cpasync16(Bs[cur ^ 1] + lr * GSTR + lw,     Bt + (size_t)(colBase + lr) * D_ + k0 + lh);
            cpasync16(Bs[cur ^ 1] + lr * GSTR + lw + 4, Bt + (size_t)(colBase + lr) * D_ + k0 + lh + 8);
            CP_COMMIT();
            CP_WAIT1();
        } else {
            CP_WAIT0();
        }
        __syncthreads();

        const unsigned aBase = (unsigned)__cvta_generic_to_shared(As[cur]);
        const unsigned bBase = (unsigned)__cvta_generic_to_shared(Bs[cur]);
#pragma unroll
        for (int kk = 0; kk < 2; ++kk) {
            const int kb = kk * 8;
            unsigned a[4][4], bf[4][2];
#pragma unroll
            for (int mt = 0; mt < 4; ++mt) {
                unsigned addr = aBase + ((wm + mt * 16 + a_row) * GSTR + kb + a_col) * 4;
                ldsm4(a[mt], addr);
            }
#pragma unroll
            for (int ntp = 0; ntp < 2; ++ntp) {
                unsigned r[4];
                unsigned addr = bBase + ((wn + ntp * 16 + b_row) * GSTR + kb + b_col) * 4;
                ldsm4(r, addr);
                bf[2 * ntp][0]     = r[0];
                bf[2 * ntp][1]     = r[1];
                bf[2 * ntp + 1][0] = r[2];
                bf[2 * ntp + 1][1] = r[3];
            }
#pragma unroll
            for (int mt = 0; mt < 4; ++mt)
#pragma unroll
                for (int nt = 0; nt < 4; ++nt)
                    mma16(acc[mt][nt], a[mt], bf[nt][0], bf[nt][1]);
        }
        __syncthreads();
    }

#pragma unroll
    for (int mt = 0; mt < 4; ++mt) {
        int r0 = rowBase + wm + mt * 16 + g;
#pragma unroll
        for (int nt = 0; nt < 4; ++nt) {
            int c0 = colBase + wn + nt * 8 + 2 * t;
            float v0 = acc[mt][nt][0], v1 = acc[mt][nt][1];
            float v2 = acc[mt][nt][2], v3 = acc[mt][nt][3];
            if (MODE == 0) {
                *(float2*)(C + (size_t)r0 * D_ + c0)       = make_float2(v0, v1);
                *(float2*)(C + (size_t)(r0 + 8) * D_ + c0) = make_float2(v2, v3);
            } else if (MODE == 2) {
                unsigned* Ch = (unsigned*)C;
                Ch[((size_t)r0 * D_ + c0) >> 1]       = h2pack(v0 * SCQ, v1 * SCQ);
                Ch[((size_t)(r0 + 8) * D_ + c0) >> 1] = h2pack(v2 * SCQ, v3 * SCQ);
            } else if (MODE == 3) {
                unsigned* Ch = (unsigned*)C;
                Ch[kfrag_word(r0, c0)]     = h2pack(v0, v1);
                Ch[kfrag_word(r0 + 8, c0)] = h2pack(v2, v3);
            } else {  // MODE 4
                __half* Chh = (__half*)C;
                Chh[vfrag_half(r0,     c0)]     = __float2half_rn(v0);
                Chh[vfrag_half(r0,     c0 + 1)] = __float2half_rn(v1);
                Chh[vfrag_half(r0 + 8, c0)]     = __float2half_rn(v2);
                Chh[vfrag_half(r0 + 8, c0 + 1)] = __float2half_rn(v3);
            }
        }
    }
}

__global__ __launch_bounds__(256, 2) void gemm_qkv()
{
    if (blockIdx.z == 0)      gemm_body<2>((const __half*)g_Xq,  (const __half*)g_Wq, g_Q);
    else if (blockIdx.z == 1) gemm_body<3>((const __half*)g_Xkv, (const __half*)g_Wk, g_K);
    else                      gemm_body<4>((const __half*)g_Xkv, (const __half*)g_Wv, g_V);
}

__global__ __launch_bounds__(256, 2) void gemm_out(float* __restrict__ out)
{
    gemm_body<0>((const __half*)g_C, (const __half*)g_Wo, out);
}

// ---------------------------------------------------------------------------
// FP16 flash attention (R13-proven, unchanged): 2 m-tiles/warp, Q in regs,
// P packs from S c-fragments, K+V double-buffered cp.async, fp16 g_C out.
// ---------------------------------------------------------------------------
#define KV_WORDS 2048
#define AK_OFF 0
#define AV_OFF (2 * KV_WORDS)
#define AMB_OFF (AV_OFF + 2 * KV_WORDS)
#define ATT_WORDS (AMB_OFF + 64)

#define M_INIT (-1.0e4f)
#define MASK_BIAS (-1.0e9f)

__global__ __launch_bounds__(128, 2) void attn_tc(
    const float* __restrict__ Q, const float* __restrict__ K,
    const float* __restrict__ V, float* __restrict__ Cout)
{
    extern __shared__ unsigned smemu[];
    unsigned* Kr = smemu + AK_OFF;
    unsigned* Vr = smemu + AV_OFF;
    float* mbias = (float*)(smemu + AMB_OFF);

    const int mtile = blockIdx.x, h = blockIdx.y, b = blockIdx.z;
    const int tid = threadIdx.x;
    const int warp = tid >> 5, lane = tid & 31;
    const int g = lane >> 2, t = lane & 3;
    const int mb = warp * 32;

    const size_t tilebase = ((size_t)(b * NH_ + h) * 32) * KV_WORDS;
    const unsigned* Kbase = (const unsigned*)K + tilebase;
    const unsigned* Vbase = (const unsigned*)V + tilebase;
    const int ld = tid * 16;

    {
#pragma unroll
        for (int i = 0; i < 4; ++i) cpasync16(Kr + ld + i * 4, Kbase + ld + i * 4);
#pragma unroll
        for (int i = 0; i < 4; ++i) cpasync16(Vr + ld + i * 4, Vbase + ld + i * 4);
    }
    CP_COMMIT();

    unsigned qa[2][4][4];
#pragma unroll
    for (int u = 0; u < 2; ++u) {
        const unsigned* q0 = (const unsigned*)Q + (size_t)(b * M_ + mtile * 128 + mb + u * 16 + g) * 512 + h * 32;
        const unsigned* q1 = (const unsigned*)Q + (size_t)(b * M_ + mtile * 128 + mb + u * 16 + g + 8) * 512 + h * 32;
#pragma unroll
        for (int kk = 0; kk < 4; ++kk) {
            qa[u][kk][0] = q0[kk * 8 + t];
            qa[u][kk][1] = q1[kk * 8 + t];
            qa[u][kk][2] = q0[kk * 8 + 4 + t];
            qa[u][kk][3] = q1[kk * 8 + 4 + t];
        }
    }

    float mS[2][2], lS[2][2];
#pragma unroll
    for (int u = 0; u < 2; ++u) { mS[u][0] = M_INIT; mS[u][1] = M_INIT; lS[u][0] = 0.f; lS[u][1] = 0.f; }
    float o[2][8][4];
#pragma unroll
    for (int u = 0; u < 2; ++u)
#pragma unroll
        for (int i = 0; i < 8; ++i)
#pragma unroll
            for (int j = 0; j < 4; ++j) o[u][i][j] = 0.f;

    const int NT = N_ / 64;  // 32
    for (int kt = 0; kt < NT; ++kt) {
        const int cur = kt & 1;
        if (kt + 1 < NT) {
            const unsigned* ks = Kbase + (size_t)(kt + 1) * KV_WORDS + ld;
            const unsigned* vs = Vbase + (size_t)(kt + 1) * KV_WORDS + ld;
            unsigned* kd = Kr + (cur ^ 1) * KV_WORDS + ld;
            unsigned* vd = Vr + (cur ^ 1) * KV_WORDS + ld;
#pragma unroll
            for (int i = 0; i < 4; ++i) cpasync16(kd + i * 4, ks + i * 4);
#pragma unroll
            for (int i = 0; i < 4; ++i) cpasync16(vd + i * 4, vs + i * 4);
            CP_COMMIT();
        }
        if (tid < 64)
            mbias[tid] = g_mask[b * N_ + kt * 64 + tid] ? MASK_BIAS : 0.f;
        if (kt + 1 < NT) CP_WAIT1(); else CP_WAIT0();
        __syncthreads();

        const unsigned* Kc = Kr + cur * KV_WORDS;
        const unsigned* Vc = Vr + cur * KV_WORDS;

        float s[2][8][4];
#pragma unroll
        for (int u = 0; u < 2; ++u)
#pragma unroll
            for (int i = 0; i < 8; ++i)
#pragma unroll
                for (int j = 0; j < 4; ++j) s[u][i][j] = 0.f;

#pragma unroll
        for (int kk = 0; kk < 4; ++kk) {
#pragma unroll
            for (int ntp = 0; ntp < 4; ++ntp) {
                uint4 bv = *(const uint4*)(Kc + ((kk * 4 + ntp) * 32 + lane) * 4);
                mma16(s[0][2 * ntp],     qa[0][kk], bv.x, bv.y);
                mma16(s[1][2 * ntp],     qa[1][kk], bv.x, bv.y);
                mma16(s[0][2 * ntp + 1], qa[0][kk], bv.z, bv.w);
                mma16(s[1][2 * ntp + 1], qa[1][kk], bv.z, bv.w);
            }
        }

#pragma unroll
        for (int u = 0; u < 2; ++u) {
            float mx0 = -3.0e38f, mx1 = -3.0e38f;
#pragma unroll
            for (int nt = 0; nt < 8; ++nt) {
                float b0 = mbias[nt * 8 + 2 * t];
                float b1 = mbias[nt * 8 + 2 * t + 1];
                s[u][nt][0] += b0; s[u][nt][1] += b1;
                s[u][nt][2] += b0; s[u][nt][3] += b1;
                mx0 = fmaxf(mx0, fmaxf(s[u][nt][0], s[u][nt][1]));
                mx1 = fmaxf(mx1, fmaxf(s[u][nt][2], s[u][nt][3]));
            }
            mx0 = fmaxf(mx0, __shfl_xor_sync(0xFFFFFFFFu, mx0, 1));
            mx0 = fmaxf(mx0, __shfl_xor_sync(0xFFFFFFFFu, mx0, 2));
            mx1 = fmaxf(mx1, __shfl_xor_sync(0xFFFFFFFFu, mx1, 1));
            mx1 = fmaxf(mx1, __shfl_xor_sync(0xFFFFFFFFu, mx1, 2));
            float nm0 = fmaxf(mS[u][0], mx0), nm1 = fmaxf(mS[u][1], mx1);
            float cr0 = ex2(mS[u][0] - nm0), cr1 = ex2(mS[u][1] - nm1);
            mS[u][0] = nm0; mS[u][1] = nm1;

            float rs0 = 0.f, rs1 = 0.f;
#pragma unroll
            for (int nt = 0; nt < 8; ++nt) {
                s[u][nt][0] = ex2(s[u][nt][0] - nm0);
                s[u][nt][1] = ex2(s[u][nt][1] - nm0);
                s[u][nt][2] = ex2(s[u][nt][2] - nm1);
                s[u][nt][3] = ex2(s[u][nt][3] - nm1);
                rs0 += s[u][nt][0] + s[u][nt][1];
                rs1 += s[u][nt][2] + s[u][nt][3];
                o[u][nt][0] *= cr0; o[u][nt][1] *= cr0;
                o[u][nt][2] *= cr1; o[u][nt][3] *= cr1;
            }
            lS[u][0] = lS[u][0] * cr0 + rs0;
            lS[u][1] = lS[u][1] * cr1 + rs1;
        }

#pragma unroll
        for (int kk2 = 0; kk2 < 4; ++kk2) {
            unsigned a[2][4];
#pragma unroll
            for (int u = 0; u < 2; ++u) {
                a[u][0] = h2pack(s[u][2 * kk2][0],     s[u][2 * kk2][1]);
                a[u][1] = h2pack(s[u][2 * kk2][2],     s[u][2 * kk2][3]);
                a[u][2] = h2pack(s[u][2 * kk2 + 1][0], s[u][2 * kk2 + 1][1]);
                a[u][3] = h2pack(s[u][2 * kk2 + 1][2], s[u][2 * kk2 + 1][3]);
            }
#pragma unroll
            for (int ntp = 0; ntp < 4; ++ntp) {
                uint4 bv = *(const uint4*)(Vc + ((kk2 * 4 + ntp) * 32 + lane) * 4);
                mma16(o[0][2 * ntp],     a[0], bv.x, bv.y);
                mma16(o[1][2 * ntp],     a[1], bv.x, bv.y);
                mma16(o[0][2 * ntp + 1], a[0], bv.z, bv.w);
                mma16(o[1][2 * ntp + 1], a[1], bv.z, bv.w);
            }
        }
        __syncthreads();
    }

#pragma unroll
    for (int u = 0; u < 2; ++u) {
        float l0 = lS[u][0], l1 = lS[u][1];
        l0 += __shfl_xor_sync(0xFFFFFFFFu, l0, 1);
        l0 += __shfl_xor_sync(0xFFFFFFFFu, l0, 2);
        l1 += __shfl_xor_sync(0xFFFFFFFFu, l1, 1);
        l1 += __shfl_xor_sync(0xFFFFFFFFu, l1, 2);
        float inv0 = 1.f / l0, inv1 = 1.f / l1;

        const int gr0 = mtile * 128 + mb + u * 16 + g;
        const int gr1 = gr0 + 8;
        unsigned* Ch = (unsigned*)Cout;
#pragma unroll
        for (int nt = 0; nt < 8; ++nt) {
            int col = h * DH_ + nt * 8 + 2 * t;
            Ch[((size_t)(b * M_ + gr0) * D_ + col) >> 1] =
                h2pack(o[u][nt][0] * inv0, o[u][nt][1] * inv0);
            Ch[((size_t)(b * M_ + gr1) * D_ + col) >> 1] =
                h2pack(o[u][nt][2] * inv1, o[u][nt][3] * inv1);
        }
    }
}

// ---------------------------------------------------------------------------
// Launch. Inputs: query, key_value, key_padding_mask, W_Q, W_K, W_V, W_O
// ---------------------------------------------------------------------------
extern "C" void kernel_launch(void* const* d_in, const int* in_sizes, int n_in,
                              void* d_out, int out_size)
{
    const float* query = (const float*)d_in[0];
    const float* keyv  = (const float*)d_in[1];
    const unsigned char* mask_raw = (const unsigned char*)d_in[2];
    const float* W_Q = (const float*)d_in[3];
    const float* W_K = (const float*)d_in[4];
    const float* W_V = (const float*)d_in[5];
    const float* W_O = (const float*)d_in[6];
    float* out = (float*)d_out;

    float *gQ, *gK, *gV, *gC;
    cudaGetSymbolAddress((void**)&gQ, g_Q);
    cudaGetSymbolAddress((void**)&gK, g_K);
    cudaGetSymbolAddress((void**)&gV, g_V);
    cudaGetSymbolAddress((void**)&gC, g_C);

    cudaFuncSetAttribute(attn_tc, cudaFuncAttributeMaxDynamicSharedMemorySize,
                         ATT_WORDS * 4);

    mask_expand_kernel<<<1, 1024>>>(mask_raw);

    // fp16 conversion of inputs (coalesced) + weight transpose (smem tiles)
    {
        const size_t total4 = (2 * NIN) / 4;
        int blocks = (int)((total4 + 255) / 256);
        preround_kernel<<<blocks, 256>>>(query, keyv);
        dim3 wt(D_ / 32, D_ / 32, 4);
        wtrans_kernel<<<wt, dim3(32, 8)>>>(W_Q, W_K, W_V, W_O);
    }

    dim3 gqkv(D_ / 128, (B_ * M_) / 128, 3);
    gemm_qkv<<<gqkv, 256>>>();

    dim3 gattn(M_ / 128, NH_, B_);
    attn_tc<<<gattn, 128, ATT_WORDS * 4>>>(gQ, gK, gV, gC);

    dim3 gout(D_ / 128, (B_ * M_) / 128);
    gemm_out<<<gout, 256>>>(out);
}

// round 17
// speedup vs baseline: 1.8168x; 1.0553x over previous
#include <cuda_runtime.h>
#include <cuda_fp16.h>
#include <stdint.h>

#define B_  2
#define M_  2048
#define N_  2048
#define D_  1024
#define NH_ 16
#define DH_ 64

#define NIN ((size_t)B_ * M_ * D_)   // 4M elems
#define NW  ((size_t)D_ * D_)        // 1M elems

// Scratch (device globals: no allocation allowed).
// g_Q: fp16(Q*scale*log2e) row-major. g_K/g_V: fp16 MMA fragment order.
// g_C: fp16 row-major (attention out). g_Xq/g_Xkv: fp16 row-major inputs.
// g_W*: fp16 TRANSPOSED [N,K] weights. (Declared float; used as half.)
__device__ float g_Q[NIN];
__device__ float g_K[NIN];
__device__ float g_V[NIN];
__device__ float g_C[NIN];
__device__ float g_Xq[NIN];
__device__ float g_Xkv[NIN];
__device__ float g_Wq[NW], g_Wk[NW], g_Wv[NW], g_Wo[NW];
__device__ unsigned char g_mask[B_ * N_];

// ---------------------------------------------------------------------------
// helpers
// ---------------------------------------------------------------------------
__device__ __forceinline__ float ex2(float x) {
    float y; asm("ex2.approx.f32 %0, %1;" : "=f"(y) : "f"(x)); return y;
}
__device__ __forceinline__ unsigned h2pack(float lo, float hi) {
    unsigned d;
    asm("cvt.rn.f16x2.f32 %0, %1, %2;" : "=r"(d) : "f"(hi), "f"(lo));
    return d;
}
__device__ __forceinline__ void mma16(float* c, const unsigned* a, unsigned b0, unsigned b1) {
    asm volatile(
        "mma.sync.aligned.m16n8k16.row.col.f32.f16.f16.f32 "
        "{%0,%1,%2,%3},{%4,%5,%6,%7},{%8,%9},{%0,%1,%2,%3};\n"
        : "+f"(c[0]), "+f"(c[1]), "+f"(c[2]), "+f"(c[3])
        : "r"(a[0]), "r"(a[1]), "r"(a[2]), "r"(a[3]), "r"(b0), "r"(b1));
}
__device__ __forceinline__ void ldsm4(unsigned* r, unsigned saddr) {
    asm volatile("ldmatrix.sync.aligned.m8n8.x4.shared.b16 {%0,%1,%2,%3}, [%4];"
                 : "=r"(r[0]), "=r"(r[1]), "=r"(r[2]), "=r"(r[3]) : "r"(saddr));
}
__device__ __forceinline__ void cpasync16(void* dst, const void* src) {
    unsigned d = (unsigned)__cvta_generic_to_shared(dst);
    asm volatile("cp.async.cg.shared.global [%0], [%1], 16;\n" :: "r"(d), "l"(src));
}
#define CP_COMMIT() asm volatile("cp.async.commit_group;\n" ::: "memory")
#define CP_WAIT0()  asm volatile("cp.async.wait_group 0;\n" ::: "memory")
#define CP_WAIT1()  asm volatile("cp.async.wait_group 1;\n" ::: "memory")

#define SCQ (0.125f * 1.44269504f)   // 1/sqrt(dh) * log2(e), folded into Q

// ---------------------------------------------------------------------------
// fp16 fragment-order indices (R13-proven).
__device__ __forceinline__ size_t kfrag_word(int R, int c) {
    int b = R >> 11, key = R & 2047, kt = key >> 6, ky = key & 63;
    int h = c >> 6, d = c & 63;
    int kk = d >> 4, dd = d & 15;
    int bsel = dd >> 3, tq = (dd & 7) >> 1;
    int nt = ky >> 3, g = ky & 7;
    int lane = g * 4 + tq;
    int ntp = nt >> 1, j = (nt & 1) * 2 + bsel;
    int word = ((kk * 4 + ntp) * 32 + lane) * 4 + j;
    return ((size_t)((b * NH_ + h) * 32 + kt)) * 2048 + word;
}
__device__ __forceinline__ size_t vfrag_half(int R, int c) {
    int b = R >> 11, key = R & 2047, kt = key >> 6, ky = key & 63;
    int h = c >> 6, d = c & 63;
    int kk = ky >> 4, kyd = ky & 15;
    int bsel = kyd >> 3, tq = (kyd & 7) >> 1, hs = kyd & 1;
    int nt = d >> 3, g = d & 7;
    int lane = g * 4 + tq;
    int ntp = nt >> 1, j = (nt & 1) * 2 + bsel;
    int word = ((kk * 4 + ntp) * 32 + lane) * 4 + j;
    return ((size_t)((b * NH_ + h) * 32 + kt)) * 4096 + (size_t)word * 2 + hs;
}

// ---------------------------------------------------------------------------
// Mask dtype sniffer + expander (bool may arrive as u8 / i32 / f32)
// ---------------------------------------------------------------------------
__global__ void mask_expand_kernel(const unsigned char* __restrict__ raw) {
    __shared__ int s_not_int, s_not_float;
    if (threadIdx.x == 0) { s_not_int = 0; s_not_float = 0; }
    __syncthreads();
    const unsigned int* w = (const unsigned int*)raw;
    for (int i = threadIdx.x; i < 1024; i += blockDim.x) {
        unsigned int x = w[i];
        if (x != 0u && x != 1u)          atomicOr(&s_not_int, 1);
        if (x != 0u && x != 0x3F800000u) atomicOr(&s_not_float, 1);
    }
    __syncthreads();
    int mode = (!s_not_int) ? 0 : ((!s_not_float) ? 1 : 2);
    if (mode == 2) {
        for (int i = threadIdx.x; i < B_ * N_; i += blockDim.x)
            g_mask[i] = raw[i] ? 1 : 0;
    } else {
        for (int i = threadIdx.x; i < B_ * N_; i += blockDim.x)
            g_mask[i] = w[i] ? 1 : 0;
    }
}

// ---------------------------------------------------------------------------
// One-time fp16 conversion of the two inputs (row-major, vectorized).
// ---------------------------------------------------------------------------
__global__ __launch_bounds__(256) void preround_kernel(
    const float* __restrict__ q, const float* __restrict__ kv)
{
    size_t i4 = (size_t)blockIdx.x * blockDim.x + threadIdx.x;
    const size_t total4 = (2 * NIN) / 4;
    if (i4 >= total4) return;
    size_t off = i4 * 4;
    const float* src; float* dst;
    if (off < NIN) { src = q; dst = g_Xq; }
    else           { src = kv; dst = g_Xkv; off -= NIN; }
    float4 v = *(const float4*)(src + off);
    unsigned* d = (unsigned*)dst;
    d[(off >> 1)]     = h2pack(v.x, v.y);
    d[(off >> 1) + 1] = h2pack(v.z, v.w);
}

// ---------------------------------------------------------------------------
// Weight transpose + fp16 convert: w[K,N] fp32 -> dh[N,K] fp16, coalesced
// both sides via a 32x33 smem tile. Block 32x8, grid (N/32, K/32, 4).
// ---------------------------------------------------------------------------
__global__ __launch_bounds__(256) void wtrans_kernel(
    const float* __restrict__ wq, const float* __restrict__ wk,
    const float* __restrict__ wv, const float* __restrict__ wo)
{
    __shared__ float tile[32][33];
    const float* src;
    float* dstf;
    switch (blockIdx.z) {
        case 0: src = wq; dstf = g_Wq; break;
        case 1: src = wk; dstf = g_Wk; break;
        case 2: src = wv; dstf = g_Wv; break;
        default: src = wo; dstf = g_Wo; break;
    }
    __half* dst = (__half*)dstf;
    const int n0 = blockIdx.x * 32, k0 = blockIdx.y * 32;
    const int tx = threadIdx.x, ty = threadIdx.y;
#pragma unroll
    for (int i = 0; i < 4; ++i)
        tile[ty + 8 * i][tx] = src[(size_t)(k0 + ty + 8 * i) * D_ + n0 + tx];
    __syncthreads();
#pragma unroll
    for (int i = 0; i < 4; ++i)
        dst[(size_t)(n0 + ty + 8 * i) * D_ + k0 + tx] =
            __float2half_rn(tile[tx][ty + 8 * i]);
}

// ---------------------------------------------------------------------------
// FP16 GEMM: C[M,N] = A[M,K] @ Bt[N,K]^T, fragment loads via ldmatrix.x4.
// Staging buffers are DYNAMIC shared memory (one 40KB allocation shared by
// all template instantiations — static-per-instantiation smem was silently
// tripling the fused kernel's footprint to 123KB -> 1 block/SM).
// 128x128 tile, BK=32, cp.async 2-stage, 256 thr, (256,2).
// Epilogue MODE: 0 = fp32 row-major, 2 = fp16(acc*SCQ) row-major,
//                3 = fp16 K fragment order, 4 = fp16 V fragment order.
// ---------------------------------------------------------------------------
#define GSTR 20
#define GT_WORDS (128 * GSTR)
#define GEMM_SMEM_BYTES (4 * GT_WORDS * 4)   // As[2] + Bs[2] = 40960 B

template<int MODE>
__device__ __forceinline__ void gemm_body(
    const __half* __restrict__ A, const __half* __restrict__ Bt, float* __restrict__ C)
{
    extern __shared__ unsigned gsm[];
    unsigned* Asm[2] = { gsm,                gsm + GT_WORDS };
    unsigned* Bsm[2] = { gsm + 2 * GT_WORDS, gsm + 3 * GT_WORDS };

    const int tid  = threadIdx.x;
    const int warp = tid >> 5, lane = tid & 31;
    const int g = lane >> 2, t = lane & 3;
    const int wm = (warp >> 2) * 64;
    const int wn = (warp & 3) * 32;
    const int rowBase = blockIdx.y * 128;
    const int colBase = blockIdx.x * 128;
    const int lr = tid >> 1;             // loader row 0..127
    const int lw = (tid & 1) * 8;        // loader WORD offset
    const int lh = lw * 2;               // loader half offset

    const int a_row = lane & 15;
    const int a_col = (lane & 16) ? 4 : 0;
    const int b_row = (lane & 7) + ((lane & 16) ? 8 : 0);
    const int b_col = (lane & 8) ? 4 : 0;

    float acc[4][4][4];
#pragma unroll
    for (int i = 0; i < 4; ++i)
#pragma unroll
        for (int j = 0; j < 4; ++j)
#pragma unroll
            for (int k = 0; k < 4; ++k) acc[i][j][k] = 0.f;

    {
        cpasync16(Asm[0] + lr * GSTR + lw,     A + (size_t)(rowBase + lr) * D_ + lh);
        cpasync16(Asm[0] + lr * GSTR + lw + 4, A + (size_t)(rowBase + lr) * D_ + lh + 8);
        cpasync16(Bsm[0] + lr * GSTR + lw,     Bt + (size_t)(colBase + lr) * D_ + lh);
        cpasync16(Bsm[0] + lr * GSTR + lw + 4, Bt + (size_t)(colBase + lr) * D_ + lh + 8);
    }
    CP_COMMIT();

    const int NIT = D_ / 32;   // 32
    for (int it = 0; it < NIT; ++it) {
        const int cur = it & 1;
        if (it + 1 < NIT) {
            const int k0 = (it + 1) * 32;
            cpasync16(Asm[cur ^ 1] + lr * GSTR + lw,     A + (size_t)(rowBase + lr) * D_ + k0 + lh);
            cpasync16(Asm[cur ^ 1] + lr * GSTR + lw + 4, A + (size_t)(rowBase + lr) * D_ + k0 + lh + 8);
            cpasync16(Bsm[cur ^ 1] + lr * GSTR + lw,     Bt + (size_t)(colBase + lr) * D_ + k0 + lh);
            cpasync16(Bsm[cur ^ 1] + lr * GSTR + lw + 4, Bt + (size_t)(colBase + lr) * D_ + k0 + lh + 8);
            CP_COMMIT();
            CP_WAIT1();
        } else {
            CP_WAIT0();
        }
        __syncthreads();

        const unsigned aBase = (unsigned)__cvta_generic_to_shared(Asm[cur]);
        const unsigned bBase = (unsigned)__cvta_generic_to_shared(Bsm[cur]);
#pragma unroll
        for (int kk = 0; kk < 2; ++kk) {
            const int kb = kk * 8;
            unsigned a[4][4], bf[4][2];
#pragma unroll
            for (int mt = 0; mt < 4; ++mt) {
                unsigned addr = aBase + ((wm + mt * 16 + a_row) * GSTR + kb + a_col) * 4;
                ldsm4(a[mt], addr);
            }
#pragma unroll
            for (int ntp = 0; ntp < 2; ++ntp) {
                unsigned r[4];
                unsigned addr = bBase + ((wn + ntp * 16 + b_row) * GSTR + kb + b_col) * 4;
                ldsm4(r, addr);
                bf[2 * ntp][0]     = r[0];
                bf[2 * ntp][1]     = r[1];
                bf[2 * ntp + 1][0] = r[2];
                bf[2 * ntp + 1][1] = r[3];
            }
#pragma unroll
            for (int mt = 0; mt < 4; ++mt)
#pragma unroll
                for (int nt = 0; nt < 4; ++nt)
                    mma16(acc[mt][nt], a[mt], bf[nt][0], bf[nt][1]);
        }
        __syncthreads();
    }

#pragma unroll
    for (int mt = 0; mt < 4; ++mt) {
        int r0 = rowBase + wm + mt * 16 + g;
#pragma unroll
        for (int nt = 0; nt < 4; ++nt) {
            int c0 = colBase + wn + nt * 8 + 2 * t;
            float v0 = acc[mt][nt][0], v1 = acc[mt][nt][1];
            float v2 = acc[mt][nt][2], v3 = acc[mt][nt][3];
            if (MODE == 0) {
                *(float2*)(C + (size_t)r0 * D_ + c0)       = make_float2(v0, v1);
                *(float2*)(C + (size_t)(r0 + 8) * D_ + c0) = make_float2(v2, v3);
            } else if (MODE == 2) {
                unsigned* Ch = (unsigned*)C;
                Ch[((size_t)r0 * D_ + c0) >> 1]       = h2pack(v0 * SCQ, v1 * SCQ);
                Ch[((size_t)(r0 + 8) * D_ + c0) >> 1] = h2pack(v2 * SCQ, v3 * SCQ);
            } else if (MODE == 3) {
                unsigned* Ch = (unsigned*)C;
                Ch[kfrag_word(r0, c0)]     = h2pack(v0, v1);
                Ch[kfrag_word(r0 + 8, c0)] = h2pack(v2, v3);
            } else {  // MODE 4
                __half* Chh = (__half*)C;
                Chh[vfrag_half(r0,     c0)]     = __float2half_rn(v0);
                Chh[vfrag_half(r0,     c0 + 1)] = __float2half_rn(v1);
                Chh[vfrag_half(r0 + 8, c0)]     = __float2half_rn(v2);
                Chh[vfrag_half(r0 + 8, c0 + 1)] = __float2half_rn(v3);
            }
        }
    }
}

__global__ __launch_bounds__(256, 2) void gemm_qkv()
{
    if (blockIdx.z == 0)      gemm_body<2>((const __half*)g_Xq,  (const __half*)g_Wq, g_Q);
    else if (blockIdx.z == 1) gemm_body<3>((const __half*)g_Xkv, (const __half*)g_Wk, g_K);
    else                      gemm_body<4>((const __half*)g_Xkv, (const __half*)g_Wv, g_V);
}

__global__ __launch_bounds__(256, 2) void gemm_out(float* __restrict__ out)
{
    gemm_body<0>((const __half*)g_C, (const __half*)g_Wo, out);
}

// ---------------------------------------------------------------------------
// FP16 flash attention (R13-proven, unchanged): 2 m-tiles/warp, Q in regs,
// P packs from S c-fragments, K+V double-buffered cp.async, fp16 g_C out.
// ---------------------------------------------------------------------------
#define KV_WORDS 2048
#define AK_OFF 0
#define AV_OFF (2 * KV_WORDS)
#define AMB_OFF (AV_OFF + 2 * KV_WORDS)
#define ATT_WORDS (AMB_OFF + 64)

#define M_INIT (-1.0e4f)
#define MASK_BIAS (-1.0e9f)

__global__ __launch_bounds__(128, 2) void attn_tc(
    const float* __restrict__ Q, const float* __restrict__ K,
    const float* __restrict__ V, float* __restrict__ Cout)
{
    extern __shared__ unsigned smemu[];
    unsigned* Kr = smemu + AK_OFF;
    unsigned* Vr = smemu + AV_OFF;
    float* mbias = (float*)(smemu + AMB_OFF);

    const int mtile = blockIdx.x, h = blockIdx.y, b = blockIdx.z;
    const int tid = threadIdx.x;
    const int warp = tid >> 5, lane = tid & 31;
    const int g = lane >> 2, t = lane & 3;
    const int mb = warp * 32;

    const size_t tilebase = ((size_t)(b * NH_ + h) * 32) * KV_WORDS;
    const unsigned* Kbase = (const unsigned*)K + tilebase;
    const unsigned* Vbase = (const unsigned*)V + tilebase;
    const int ld = tid * 16;

    {
#pragma unroll
        for (int i = 0; i < 4; ++i) cpasync16(Kr + ld + i * 4, Kbase + ld + i * 4);
#pragma unroll
        for (int i = 0; i < 4; ++i) cpasync16(Vr + ld + i * 4, Vbase + ld + i * 4);
    }
    CP_COMMIT();

    unsigned qa[2][4][4];
#pragma unroll
    for (int u = 0; u < 2; ++u) {
        const unsigned* q0 = (const unsigned*)Q + (size_t)(b * M_ + mtile * 128 + mb + u * 16 + g) * 512 + h * 32;
        const unsigned* q1 = (const unsigned*)Q + (size_t)(b * M_ + mtile * 128 + mb + u * 16 + g + 8) * 512 + h * 32;
#pragma unroll
        for (int kk = 0; kk < 4; ++kk) {
            qa[u][kk][0] = q0[kk * 8 + t];
            qa[u][kk][1] = q1[kk * 8 + t];
            qa[u][kk][2] = q0[kk * 8 + 4 + t];
            qa[u][kk][3] = q1[kk * 8 + 4 + t];
        }
    }

    float mS[2][2], lS[2][2];
#pragma unroll
    for (int u = 0; u < 2; ++u) { mS[u][0] = M_INIT; mS[u][1] = M_INIT; lS[u][0] = 0.f; lS[u][1] = 0.f; }
    float o[2][8][4];
#pragma unroll
    for (int u = 0; u < 2; ++u)
#pragma unroll
        for (int i = 0; i < 8; ++i)
#pragma unroll
            for (int j = 0; j < 4; ++j) o[u][i][j] = 0.f;

    const int NT = N_ / 64;  // 32
    for (int kt = 0; kt < NT; ++kt) {
        const int cur = kt & 1;
        if (kt + 1 < NT) {
            const unsigned* ks = Kbase + (size_t)(kt + 1) * KV_WORDS + ld;
            const unsigned* vs = Vbase + (size_t)(kt + 1) * KV_WORDS + ld;
            unsigned* kd = Kr + (cur ^ 1) * KV_WORDS + ld;
            unsigned* vd = Vr + (cur ^ 1) * KV_WORDS + ld;
#pragma unroll
            for (int i = 0; i < 4; ++i) cpasync16(kd + i * 4, ks + i * 4);
#pragma unroll
            for (int i = 0; i < 4; ++i) cpasync16(vd + i * 4, vs + i * 4);
            CP_COMMIT();
        }
        if (tid < 64)
            mbias[tid] = g_mask[b * N_ + kt * 64 + tid] ? MASK_BIAS : 0.f;
        if (kt + 1 < NT) CP_WAIT1(); else CP_WAIT0();
        __syncthreads();

        const unsigned* Kc = Kr + cur * KV_WORDS;
        const unsigned* Vc = Vr + cur * KV_WORDS;

        float s[2][8][4];
#pragma unroll
        for (int u = 0; u < 2; ++u)
#pragma unroll
            for (int i = 0; i < 8; ++i)
#pragma unroll
                for (int j = 0; j < 4; ++j) s[u][i][j] = 0.f;

#pragma unroll
        for (int kk = 0; kk < 4; ++kk) {
#pragma unroll
            for (int ntp = 0; ntp < 4; ++ntp) {
                uint4 bv = *(const uint4*)(Kc + ((kk * 4 + ntp) * 32 + lane) * 4);
                mma16(s[0][2 * ntp],     qa[0][kk], bv.x, bv.y);
                mma16(s[1][2 * ntp],     qa[1][kk], bv.x, bv.y);
                mma16(s[0][2 * ntp + 1], qa[0][kk], bv.z, bv.w);
                mma16(s[1][2 * ntp + 1], qa[1][kk], bv.z, bv.w);
            }
        }

#pragma unroll
        for (int u = 0; u < 2; ++u) {
            float mx0 = -3.0e38f, mx1 = -3.0e38f;
#pragma unroll
            for (int nt = 0; nt < 8; ++nt) {
                float b0 = mbias[nt * 8 + 2 * t];
                float b1 = mbias[nt * 8 + 2 * t + 1];
                s[u][nt][0] += b0; s[u][nt][1] += b1;
                s[u][nt][2] += b0; s[u][nt][3] += b1;
                mx0 = fmaxf(mx0, fmaxf(s[u][nt][0], s[u][nt][1]));
                mx1 = fmaxf(mx1, fmaxf(s[u][nt][2], s[u][nt][3]));
            }
            mx0 = fmaxf(mx0, __shfl_xor_sync(0xFFFFFFFFu, mx0, 1));
            mx0 = fmaxf(mx0, __shfl_xor_sync(0xFFFFFFFFu, mx0, 2));
            mx1 = fmaxf(mx1, __shfl_xor_sync(0xFFFFFFFFu, mx1, 1));
            mx1 = fmaxf(mx1, __shfl_xor_sync(0xFFFFFFFFu, mx1, 2));
            float nm0 = fmaxf(mS[u][0], mx0), nm1 = fmaxf(mS[u][1], mx1);
            float cr0 = ex2(mS[u][0] - nm0), cr1 = ex2(mS[u][1] - nm1);
            mS[u][0] = nm0; mS[u][1] = nm1;

            float rs0 = 0.f, rs1 = 0.f;
#pragma unroll
            for (int nt = 0; nt < 8; ++nt) {
                s[u][nt][0] = ex2(s[u][nt][0] - nm0);
                s[u][nt][1] = ex2(s[u][nt][1] - nm0);
                s[u][nt][2] = ex2(s[u][nt][2] - nm1);
                s[u][nt][3] = ex2(s[u][nt][3] - nm1);
                rs0 += s[u][nt][0] + s[u][nt][1];
                rs1 += s[u][nt][2] + s[u][nt][3];
                o[u][nt][0] *= cr0; o[u][nt][1] *= cr0;
                o[u][nt][2] *= cr1; o[u][nt][3] *= cr1;
            }
            lS[u][0] = lS[u][0] * cr0 + rs0;
            lS[u][1] = lS[u][1] * cr1 + rs1;
        }

#pragma unroll
        for (int kk2 = 0; kk2 < 4; ++kk2) {
            unsigned a[2][4];
#pragma unroll
            for (int u = 0; u < 2; ++u) {
                a[u][0] = h2pack(s[u][2 * kk2][0],     s[u][2 * kk2][1]);
                a[u][1] = h2pack(s[u][2 * kk2][2],     s[u][2 * kk2][3]);
                a[u][2] = h2pack(s[u][2 * kk2 + 1][0], s[u][2 * kk2 + 1][1]);
                a[u][3] = h2pack(s[u][2 * kk2 + 1][2], s[u][2 * kk2 + 1][3]);
            }
#pragma unroll
            for (int ntp = 0; ntp < 4; ++ntp) {
                uint4 bv = *(const uint4*)(Vc + ((kk2 * 4 + ntp) * 32 + lane) * 4);
                mma16(o[0][2 * ntp],     a[0], bv.x, bv.y);
                mma16(o[1][2 * ntp],     a[1], bv.x, bv.y);
                mma16(o[0][2 * ntp + 1], a[0], bv.z, bv.w);
                mma16(o[1][2 * ntp + 1], a[1], bv.z, bv.w);
            }
        }
        __syncthreads();
    }

#pragma unroll
    for (int u = 0; u < 2; ++u) {
        float l0 = lS[u][0], l1 = lS[u][1];
        l0 += __shfl_xor_sync(0xFFFFFFFFu, l0, 1);
        l0 += __shfl_xor_sync(0xFFFFFFFFu, l0, 2);
        l1 += __shfl_xor_sync(0xFFFFFFFFu, l1, 1);
        l1 += __shfl_xor_sync(0xFFFFFFFFu, l1, 2);
        float inv0 = 1.f / l0, inv1 = 1.f / l1;

        const int gr0 = mtile * 128 + mb + u * 16 + g;
        const int gr1 = gr0 + 8;
        unsigned* Ch = (unsigned*)Cout;
#pragma unroll
        for (int nt = 0; nt < 8; ++nt) {
            int col = h * DH_ + nt * 8 + 2 * t;
            Ch[((size_t)(b * M_ + gr0) * D_ + col) >> 1] =
                h2pack(o[u][nt][0] * inv0, o[u][nt][1] * inv0);
            Ch[((size_t)(b * M_ + gr1) * D_ + col) >> 1] =
                h2pack(o[u][nt][2] * inv1, o[u][nt][3] * inv1);
        }
    }
}

// ---------------------------------------------------------------------------
// Launch. Inputs: query, key_value, key_padding_mask, W_Q, W_K, W_V, W_O
// ---------------------------------------------------------------------------
extern "C" void kernel_launch(void* const* d_in, const int* in_sizes, int n_in,
                              void* d_out, int out_size)
{
    const float* query = (const float*)d_in[0];
    const float* keyv  = (const float*)d_in[1];
    const unsigned char* mask_raw = (const unsigned char*)d_in[2];
    const float* W_Q = (const float*)d_in[3];
    const float* W_K = (const float*)d_in[4];
    const float* W_V = (const float*)d_in[5];
    const float* W_O = (const float*)d_in[6];
    float* out = (float*)d_out;

    float *gQ, *gK, *gV, *gC;
    cudaGetSymbolAddress((void**)&gQ, g_Q);
    cudaGetSymbolAddress((void**)&gK, g_K);
    cudaGetSymbolAddress((void**)&gV, g_V);
    cudaGetSymbolAddress((void**)&gC, g_C);

    cudaFuncSetAttribute(attn_tc, cudaFuncAttributeMaxDynamicSharedMemorySize,
                         ATT_WORDS * 4);

    mask_expand_kernel<<<1, 1024>>>(mask_raw);

    // fp16 conversion of inputs (coalesced) + weight transpose (smem tiles)
    {
        const size_t total4 = (2 * NIN) / 4;
        int blocks = (int)((total4 + 255) / 256);
        preround_kernel<<<blocks, 256>>>(query, keyv);
        dim3 wt(D_ / 32, D_ / 32, 4);
        wtrans_kernel<<<wt, dim3(32, 8)>>>(W_Q, W_K, W_V, W_O);
    }

    dim3 gqkv(D_ / 128, (B_ * M_) / 128, 3);
    gemm_qkv<<<gqkv, 256, GEMM_SMEM_BYTES>>>();

    dim3 gattn(M_ / 128, NH_, B_);
    attn_tc<<<gattn, 128, ATT_WORDS * 4>>>(gQ, gK, gV, gC);

    dim3 gout(D_ / 128, (B_ * M_) / 128);
    gemm_out<<<gout, 256, GEMM_SMEM_BYTES>>>(out);
}